// round 6
// baseline (speedup 1.0000x reference)
#include <cuda_runtime.h>
#include <math.h>

#define HDIM   128
#define NMAX   100000
#define EMAX   1000000
#define CDIM   16
#define SCAN_B 1024

// Scratch (static device globals — allocation-free per harness rules)
__device__ float g_dinv[NMAX];
__device__ float g_lin[(size_t)NMAX * HDIM];   // holds lin' = dinv[row] * (act(A)@W)
__device__ float g_agg[(size_t)NMAX * HDIM];
__device__ float g_P  [(size_t)NMAX * 32];     // per-node [P_src(16) | P_dst(16)]
__device__ int   g_cnt[NMAX];
__device__ int   g_rowptr[NMAX + 1];
__device__ int   g_cursor[NMAX];
__device__ int   g_csrsrc[EMAX];
__device__ int   g_blocksum[128];
__device__ int   g_blockoff[128];

// ---------------------------------------------------------------- CSR build
__global__ void k_cnt_zero(int n) {
    int i = blockIdx.x * blockDim.x + threadIdx.x;
    if (i < n) g_cnt[i] = 0;
}
__global__ void k_hist(const int* __restrict__ dst, int e) {
    int i = blockIdx.x * blockDim.x + threadIdx.x;
    if (i < e) atomicAdd(&g_cnt[dst[i]], 1);
}
__global__ void k_scan1(int n) {
    __shared__ int sm[SCAN_B];
    int i = blockIdx.x * SCAN_B + threadIdx.x;
    int v = (i < n) ? g_cnt[i] : 0;
    if (i < n) g_dinv[i] = rsqrtf((float)v + 1.0f);   // +1 self-loop
    sm[threadIdx.x] = v;
    __syncthreads();
    #pragma unroll
    for (int off = 1; off < SCAN_B; off <<= 1) {
        int t = (threadIdx.x >= off) ? sm[threadIdx.x - off] : 0;
        __syncthreads();
        sm[threadIdx.x] += t;
        __syncthreads();
    }
    if (i < n) g_rowptr[i] = sm[threadIdx.x] - v;     // exclusive
    if (threadIdx.x == SCAN_B - 1) g_blocksum[blockIdx.x] = sm[SCAN_B - 1];
}
__global__ void k_scan2(int nb) {
    __shared__ int sm[128];
    int t = threadIdx.x;
    int v = (t < nb) ? g_blocksum[t] : 0;
    sm[t] = v;
    __syncthreads();
    #pragma unroll
    for (int off = 1; off < 128; off <<= 1) {
        int x = (t >= off) ? sm[t - off] : 0;
        __syncthreads();
        sm[t] += x;
        __syncthreads();
    }
    if (t < nb) g_blockoff[t] = sm[t] - v;            // exclusive
}
__global__ void k_scan3(int n, int e) {
    int i = blockIdx.x * SCAN_B + threadIdx.x;
    if (i < n) {
        int r = g_rowptr[i] + g_blockoff[blockIdx.x];
        g_rowptr[i] = r;
        g_cursor[i] = r;
    }
    if (i == 0) g_rowptr[n] = e;
}
__global__ void k_fill(const int* __restrict__ src, const int* __restrict__ dst, int e) {
    int i = blockIdx.x * blockDim.x + threadIdx.x;
    if (i < e) {
        int pos = atomicAdd(&g_cursor[dst[i]], 1);
        g_csrsrc[pos] = src[i];
    }
}

// ---------------------------------------------------------------- GEMM: lin' = dinv[row] * (act(A) @ W)
// BM=128, 256 threads. Warp covers 16 rows (2 groups of 8) x 128 cols.
// Micro-tile 8 rows x 8 cols per thread: 1.0 B smem / FMA.
#define GEMM_BM 128
#define GEMM_SMEM ((128*128 + GEMM_BM*128) * 4)   // 128 KB
__global__ void k_gemm128(const float* __restrict__ Aext,
                          const float* __restrict__ W, int M, int relu) {
    extern __shared__ float sm[];
    float*  Ws  = sm;                 // 128*128
    float*  As  = sm + 128 * 128;     // 128*128
    float4* Ws4 = (float4*)Ws;
    float4* As4 = (float4*)As;

    const float* A = Aext ? Aext : g_agg;
    int tid = threadIdx.x;

    // load W (4096 float4, 16 per thread)
    const float4* W4 = (const float4*)W;
    #pragma unroll
    for (int i = 0; i < 16; i++) Ws4[tid + i * 256] = W4[tid + i * 256];

    // load A tile (128*32 = 4096 float4, 16 per thread), fused ReLU, zero-pad
    int row0 = blockIdx.x * GEMM_BM;
    const float4* A4 = (const float4*)A;
    #pragma unroll
    for (int i = 0; i < 16; i++) {
        int idx = tid + i * 256;       // 0..4095
        int r   = idx >> 5;
        float4 v = make_float4(0.f, 0.f, 0.f, 0.f);
        if (row0 + r < M) {
            v = A4[(size_t)(row0 + r) * 32 + (idx & 31)];
            if (relu) {
                v.x = fmaxf(v.x, 0.f); v.y = fmaxf(v.y, 0.f);
                v.z = fmaxf(v.z, 0.f); v.w = fmaxf(v.w, 0.f);
            }
        }
        As4[idx] = v;
    }
    __syncthreads();

    int warp  = tid >> 5, lane = tid & 31;
    int group = lane >> 4;            // 0/1: which 8-row subgroup
    int c     = lane & 15;            // col group: cols c*8 .. c*8+7
    int rbase = warp * 16 + group * 8;

    float4 acc[8][2];
    #pragma unroll
    for (int r = 0; r < 8; r++) {
        acc[r][0] = make_float4(0.f, 0.f, 0.f, 0.f);
        acc[r][1] = make_float4(0.f, 0.f, 0.f, 0.f);
    }

    #pragma unroll 2
    for (int k4 = 0; k4 < 32; k4++) {
        // 8 w-vectors: 4 k-steps x 2 float4 (8 cols)
        float4 w[4][2];
        #pragma unroll
        for (int kk = 0; kk < 4; kk++) {
            w[kk][0] = Ws4[(k4 * 4 + kk) * 32 + c * 2];
            w[kk][1] = Ws4[(k4 * 4 + kk) * 32 + c * 2 + 1];
        }
        #pragma unroll
        for (int r = 0; r < 8; r++) {
            float4 a = As4[(rbase + r) * 32 + k4];   // broadcast within group
            acc[r][0].x = fmaf(a.x, w[0][0].x, acc[r][0].x);
            acc[r][0].y = fmaf(a.x, w[0][0].y, acc[r][0].y);
            acc[r][0].z = fmaf(a.x, w[0][0].z, acc[r][0].z);
            acc[r][0].w = fmaf(a.x, w[0][0].w, acc[r][0].w);
            acc[r][1].x = fmaf(a.x, w[0][1].x, acc[r][1].x);
            acc[r][1].y = fmaf(a.x, w[0][1].y, acc[r][1].y);
            acc[r][1].z = fmaf(a.x, w[0][1].z, acc[r][1].z);
            acc[r][1].w = fmaf(a.x, w[0][1].w, acc[r][1].w);

            acc[r][0].x = fmaf(a.y, w[1][0].x, acc[r][0].x);
            acc[r][0].y = fmaf(a.y, w[1][0].y, acc[r][0].y);
            acc[r][0].z = fmaf(a.y, w[1][0].z, acc[r][0].z);
            acc[r][0].w = fmaf(a.y, w[1][0].w, acc[r][0].w);
            acc[r][1].x = fmaf(a.y, w[1][1].x, acc[r][1].x);
            acc[r][1].y = fmaf(a.y, w[1][1].y, acc[r][1].y);
            acc[r][1].z = fmaf(a.y, w[1][1].z, acc[r][1].z);
            acc[r][1].w = fmaf(a.y, w[1][1].w, acc[r][1].w);

            acc[r][0].x = fmaf(a.z, w[2][0].x, acc[r][0].x);
            acc[r][0].y = fmaf(a.z, w[2][0].y, acc[r][0].y);
            acc[r][0].z = fmaf(a.z, w[2][0].z, acc[r][0].z);
            acc[r][0].w = fmaf(a.z, w[2][0].w, acc[r][0].w);
            acc[r][1].x = fmaf(a.z, w[2][1].x, acc[r][1].x);
            acc[r][1].y = fmaf(a.z, w[2][1].y, acc[r][1].y);
            acc[r][1].z = fmaf(a.z, w[2][1].z, acc[r][1].z);
            acc[r][1].w = fmaf(a.z, w[2][1].w, acc[r][1].w);

            acc[r][0].x = fmaf(a.w, w[3][0].x, acc[r][0].x);
            acc[r][0].y = fmaf(a.w, w[3][0].y, acc[r][0].y);
            acc[r][0].z = fmaf(a.w, w[3][0].z, acc[r][0].z);
            acc[r][0].w = fmaf(a.w, w[3][0].w, acc[r][0].w);
            acc[r][1].x = fmaf(a.w, w[3][1].x, acc[r][1].x);
            acc[r][1].y = fmaf(a.w, w[3][1].y, acc[r][1].y);
            acc[r][1].z = fmaf(a.w, w[3][1].z, acc[r][1].z);
            acc[r][1].w = fmaf(a.w, w[3][1].w, acc[r][1].w);
        }
    }

    float4* O4 = (float4*)g_lin;
    #pragma unroll
    for (int r = 0; r < 8; r++) {
        int row = row0 + rbase + r;
        if (row < M) {
            float dv = g_dinv[row];
            float4 o0 = acc[r][0], o1 = acc[r][1];
            o0.x *= dv; o0.y *= dv; o0.z *= dv; o0.w *= dv;
            o1.x *= dv; o1.y *= dv; o1.z *= dv; o1.w *= dv;
            O4[(size_t)row * 32 + c * 2]     = o0;
            O4[(size_t)row * 32 + c * 2 + 1] = o1;
        }
    }
}

// ---------------------------------------------------------------- aggregate: agg[d] = b + dinv[d]*(lin'[d] + sum lin'[s])
// Uniform (broadcast) index loads, no shuffles; unroll-4 for MLP.
__global__ void k_aggregate(const float* __restrict__ b, int n) {
    int gwarp = (blockIdx.x * blockDim.x + threadIdx.x) >> 5;
    int lane  = threadIdx.x & 31;
    if (gwarp >= n) return;

    const float4* lin4 = (const float4*)g_lin;
    float4 acc = lin4[(size_t)gwarp * 32 + lane];   // self term (already dinv-scaled)

    int beg = g_rowptr[gwarp];
    int end = g_rowptr[gwarp + 1];
    int j = beg;
    for (; j + 4 <= end; j += 4) {
        int s0 = g_csrsrc[j];
        int s1 = g_csrsrc[j + 1];
        int s2 = g_csrsrc[j + 2];
        int s3 = g_csrsrc[j + 3];
        float4 v0 = lin4[(size_t)s0 * 32 + lane];
        float4 v1 = lin4[(size_t)s1 * 32 + lane];
        float4 v2 = lin4[(size_t)s2 * 32 + lane];
        float4 v3 = lin4[(size_t)s3 * 32 + lane];
        acc.x += v0.x + v1.x + v2.x + v3.x;
        acc.y += v0.y + v1.y + v2.y + v3.y;
        acc.z += v0.z + v1.z + v2.z + v3.z;
        acc.w += v0.w + v1.w + v2.w + v3.w;
    }
    for (; j < end; j++) {
        int s = g_csrsrc[j];
        float4 v = lin4[(size_t)s * 32 + lane];
        acc.x += v.x; acc.y += v.y; acc.z += v.z; acc.w += v.w;
    }

    float di = g_dinv[gwarp];
    float4 bb = ((const float4*)b)[lane];
    float4 o;
    o.x = fmaf(acc.x, di, bb.x);
    o.y = fmaf(acc.y, di, bb.y);
    o.z = fmaf(acc.z, di, bb.z);
    o.w = fmaf(acc.w, di, bb.w);
    ((float4*)g_agg)[(size_t)gwarp * 32 + lane] = o;
}

// ---------------------------------------------------------------- node projection as blocked GEMM:
// P[n, 32] = relu(g_agg[n,128]) @ Wp[128,32], Wp packed from Wfc rows 0..255.
#define PROJ_BM 64
__global__ void k_proj(const float* __restrict__ Wfc, int n) {
    __shared__ float Ws[128 * 32];        // Ws[k*32 + l]
    __shared__ float As[PROJ_BM * 128];   // 32 KB

    int tid = threadIdx.x;
    for (int idx = tid; idx < 128 * 32; idx += 256) {
        int k = idx >> 5, l = idx & 31;
        Ws[idx] = (l < 16) ? Wfc[k * 16 + l] : Wfc[(128 + k) * 16 + (l - 16)];
    }

    int row0 = blockIdx.x * PROJ_BM;
    float4* As4 = (float4*)As;
    const float4* A4 = (const float4*)g_agg;
    #pragma unroll
    for (int i = 0; i < 8; i++) {
        int idx = tid + i * 256;          // 0..2047
        int r   = idx >> 5;
        float4 v = make_float4(0.f, 0.f, 0.f, 0.f);
        if (row0 + r < n) {
            v = A4[(size_t)(row0 + r) * 32 + (idx & 31)];
            v.x = fmaxf(v.x, 0.f); v.y = fmaxf(v.y, 0.f);
            v.z = fmaxf(v.z, 0.f); v.w = fmaxf(v.w, 0.f);
        }
        As4[idx] = v;
    }
    __syncthreads();

    int warp = tid >> 5, lane = tid & 31;
    int rbase = warp * 8;

    float acc[8];
    #pragma unroll
    for (int r = 0; r < 8; r++) acc[r] = 0.f;

    #pragma unroll 4
    for (int k4 = 0; k4 < 32; k4++) {
        float w0 = Ws[(k4 * 4 + 0) * 32 + lane];
        float w1 = Ws[(k4 * 4 + 1) * 32 + lane];
        float w2 = Ws[(k4 * 4 + 2) * 32 + lane];
        float w3 = Ws[(k4 * 4 + 3) * 32 + lane];
        #pragma unroll
        for (int r = 0; r < 8; r++) {
            float4 a = As4[(rbase + r) * 32 + k4];
            acc[r] = fmaf(a.x, w0, acc[r]);
            acc[r] = fmaf(a.y, w1, acc[r]);
            acc[r] = fmaf(a.z, w2, acc[r]);
            acc[r] = fmaf(a.w, w3, acc[r]);
        }
    }

    #pragma unroll
    for (int r = 0; r < 8; r++) {
        int row = row0 + rbase + r;
        if (row < n) g_P[(size_t)row * 32 + lane] = acc[r];
    }
}

// ---------------------------------------------------------------- edge output: out = logsoftmax(P_src[s] + P_dst[d] + ea@We + b)
#define EB 16   // edges per block (256 threads = 16 edges x 16 classes)
__global__ void k_edge2(const int* __restrict__ src, const int* __restrict__ dst,
                        const float* __restrict__ eattr,
                        const float* __restrict__ Wfc, const float* __restrict__ bfc,
                        float* __restrict__ out, int e) {
    __shared__ float We[32 * 16];    // Wfc rows 256..287
    __shared__ float bs[CDIM];
    __shared__ float ea[EB][33];     // padded to kill bank conflicts

    int tid = threadIdx.x;
    for (int i = tid; i < 32 * 16; i += 256) We[i] = Wfc[256 * 16 + i];
    if (tid < CDIM) bs[tid] = bfc[tid];

    int e0 = blockIdx.x * EB;
    if (tid < 128) {
        int el = tid >> 3, q = tid & 7;
        if (e0 + el < e) {
            float4 v = ((const float4*)(eattr + (size_t)(e0 + el) * 32))[q];
            ea[el][q * 4 + 0] = v.x; ea[el][q * 4 + 1] = v.y;
            ea[el][q * 4 + 2] = v.z; ea[el][q * 4 + 3] = v.w;
        }
    }
    __syncthreads();

    int el = tid >> 4, c = tid & 15;
    int edge = e0 + el;
    bool valid = edge < e;
    int ce = valid ? edge : e - 1;

    int s = src[ce], d = dst[ce];
    float acc = bs[c] + g_P[(size_t)s * 32 + c] + g_P[(size_t)d * 32 + 16 + c];
    #pragma unroll
    for (int k = 0; k < 32; k++)
        acc = fmaf(ea[el][k], We[k * 16 + c], acc);

    float m = acc;
    #pragma unroll
    for (int off = 8; off; off >>= 1)
        m = fmaxf(m, __shfl_xor_sync(0xffffffffu, m, off));
    float ex = __expf(acc - m);
    float ss = ex;
    #pragma unroll
    for (int off = 8; off; off >>= 1)
        ss += __shfl_xor_sync(0xffffffffu, ss, off);
    float res = acc - m - __logf(ss);
    if (valid) out[(size_t)edge * CDIM + c] = res;
}

// ---------------------------------------------------------------- launch
extern "C" void kernel_launch(void* const* d_in, const int* in_sizes, int n_in,
                              void* d_out, int out_size) {
    const float* x     = (const float*)d_in[0];
    const int*   ei    = (const int*)  d_in[1];
    const float* eattr = (const float*)d_in[2];
    const float* W1 = (const float*)d_in[3];  const float* b1 = (const float*)d_in[4];
    const float* W2 = (const float*)d_in[5];  const float* b2 = (const float*)d_in[6];
    const float* W3 = (const float*)d_in[7];  const float* b3 = (const float*)d_in[8];
    const float* Wfc = (const float*)d_in[9]; const float* bfc = (const float*)d_in[10];
    float* out = (float*)d_out;

    int n = in_sizes[0] / HDIM;
    int e = in_sizes[1] / 2;
    const int* src = ei;
    const int* dst = ei + e;

    cudaFuncSetAttribute(k_gemm128, cudaFuncAttributeMaxDynamicSharedMemorySize, GEMM_SMEM);

    int bn   = (n + 255) / 256;
    int be   = (e + 255) / 256;
    int bgem = (n + GEMM_BM - 1) / GEMM_BM;
    int bagg = (n + 7) / 8;
    int bedg = (e + EB - 1) / EB;
    int nscan = (n + SCAN_B - 1) / SCAN_B;

    // ---- CSR build (once; reused by all 3 layers) + degree norm
    k_cnt_zero<<<bn, 256>>>(n);
    k_hist    <<<be, 256>>>(dst, e);
    k_scan1   <<<nscan, SCAN_B>>>(n);
    k_scan2   <<<1, 128>>>(nscan);
    k_scan3   <<<nscan, SCAN_B>>>(n, e);
    k_fill    <<<be, 256>>>(src, dst, e);

    // ---- 3 GCN layers (lin' pre-scaled by dinv in GEMM epilogue)
    k_gemm128  <<<bgem, 256, GEMM_SMEM>>>(x, W1, n, 0);
    k_aggregate<<<bagg, 256>>>(b1, n);

    k_gemm128  <<<bgem, 256, GEMM_SMEM>>>(nullptr, W2, n, 1);
    k_aggregate<<<bagg, 256>>>(b2, n);

    k_gemm128  <<<bgem, 256, GEMM_SMEM>>>(nullptr, W3, n, 1);
    k_aggregate<<<bagg, 256>>>(b3, n);

    // ---- factored edge classifier
    k_proj <<<(n + PROJ_BM - 1) / PROJ_BM, 256>>>(Wfc, n);
    k_edge2<<<bedg, 256>>>(src, dst, eattr, Wfc, bfc, out, e);
}

// round 7
// speedup vs baseline: 1.1556x; 1.1556x over previous
#include <cuda_runtime.h>
#include <math.h>

#define HDIM   128
#define NMAX   100000
#define EMAX   1000000
#define CDIM   16
#define SCAN_B 1024

// Scratch (static device globals — allocation-free per harness rules)
__device__ float g_dinv[NMAX];
__device__ float g_lin[(size_t)NMAX * HDIM];   // holds lin' = dinv[row] * (act(A)@W)
__device__ float g_agg[(size_t)NMAX * HDIM];
__device__ float g_P  [(size_t)NMAX * 32];     // per-node [P_src(16) | P_dst(16)]
__device__ int   g_cnt[NMAX];
__device__ int   g_rowptr[NMAX + 1];
__device__ int   g_cursor[NMAX];
__device__ int   g_csrsrc[EMAX];
__device__ int   g_blocksum[128];
__device__ int   g_blockoff[128];

// ---------------------------------------------------------------- CSR build
__global__ void k_cnt_zero(int n) {
    int i = blockIdx.x * blockDim.x + threadIdx.x;
    if (i < n) g_cnt[i] = 0;
}
__global__ void k_hist(const int* __restrict__ dst, int e) {
    int i = blockIdx.x * blockDim.x + threadIdx.x;
    if (i < e) atomicAdd(&g_cnt[dst[i]], 1);
}
__global__ void k_scan1(int n) {
    __shared__ int sm[SCAN_B];
    int i = blockIdx.x * SCAN_B + threadIdx.x;
    int v = (i < n) ? g_cnt[i] : 0;
    if (i < n) g_dinv[i] = rsqrtf((float)v + 1.0f);   // +1 self-loop
    sm[threadIdx.x] = v;
    __syncthreads();
    #pragma unroll
    for (int off = 1; off < SCAN_B; off <<= 1) {
        int t = (threadIdx.x >= off) ? sm[threadIdx.x - off] : 0;
        __syncthreads();
        sm[threadIdx.x] += t;
        __syncthreads();
    }
    if (i < n) g_rowptr[i] = sm[threadIdx.x] - v;     // exclusive
    if (threadIdx.x == SCAN_B - 1) g_blocksum[blockIdx.x] = sm[SCAN_B - 1];
}
__global__ void k_scan2(int nb) {
    __shared__ int sm[128];
    int t = threadIdx.x;
    int v = (t < nb) ? g_blocksum[t] : 0;
    sm[t] = v;
    __syncthreads();
    #pragma unroll
    for (int off = 1; off < 128; off <<= 1) {
        int x = (t >= off) ? sm[t - off] : 0;
        __syncthreads();
        sm[t] += x;
        __syncthreads();
    }
    if (t < nb) g_blockoff[t] = sm[t] - v;            // exclusive
}
__global__ void k_scan3(int n, int e) {
    int i = blockIdx.x * SCAN_B + threadIdx.x;
    if (i < n) {
        int r = g_rowptr[i] + g_blockoff[blockIdx.x];
        g_rowptr[i] = r;
        g_cursor[i] = r;
    }
    if (i == 0) g_rowptr[n] = e;
}
__global__ void k_fill(const int* __restrict__ src, const int* __restrict__ dst, int e) {
    int i = blockIdx.x * blockDim.x + threadIdx.x;
    if (i < e) {
        int pos = atomicAdd(&g_cursor[dst[i]], 1);
        g_csrsrc[pos] = src[i];
    }
}

// ---------------------------------------------------------------- GEMM: lin' = dinv[row] * (act(A) @ W)
// Round-5 proven config: BM=64, 96 KB smem (2 CTAs/SM), 8 rows x 4 cols/thread.
#define GEMM_BM 64
#define GEMM_SMEM ((128*128 + GEMM_BM*128) * 4)
__global__ void k_gemm128(const float* __restrict__ Aext,
                          const float* __restrict__ W, int M, int relu) {
    extern __shared__ float sm[];
    float*  Ws  = sm;                 // 128*128
    float*  As  = sm + 128 * 128;     // BM*128
    float4* Ws4 = (float4*)Ws;
    float4* As4 = (float4*)As;

    const float* A = Aext ? Aext : g_agg;
    int tid = threadIdx.x;

    const float4* W4 = (const float4*)W;
    #pragma unroll
    for (int i = 0; i < 16; i++) Ws4[tid + i * 256] = W4[tid + i * 256];

    int row0 = blockIdx.x * GEMM_BM;
    const float4* A4 = (const float4*)A;
    #pragma unroll
    for (int i = 0; i < 8; i++) {
        int idx = tid + i * 256;       // 0..2047
        int r   = idx >> 5;
        float4 v = make_float4(0.f, 0.f, 0.f, 0.f);
        if (row0 + r < M) {
            v = A4[(size_t)(row0 + r) * 32 + (idx & 31)];
            if (relu) {
                v.x = fmaxf(v.x, 0.f); v.y = fmaxf(v.y, 0.f);
                v.z = fmaxf(v.z, 0.f); v.w = fmaxf(v.w, 0.f);
            }
        }
        As4[idx] = v;
    }
    __syncthreads();

    int warp = tid >> 5, lane = tid & 31;
    int rbase = warp * 8;

    float4 acc[8];
    #pragma unroll
    for (int r = 0; r < 8; r++) acc[r] = make_float4(0.f, 0.f, 0.f, 0.f);

    // k processed 4 at a time: A fetched as one float4 broadcast per row
    #pragma unroll 4
    for (int k4 = 0; k4 < 32; k4++) {
        float4 w0 = Ws4[(k4 * 4 + 0) * 32 + lane];
        float4 w1 = Ws4[(k4 * 4 + 1) * 32 + lane];
        float4 w2 = Ws4[(k4 * 4 + 2) * 32 + lane];
        float4 w3 = Ws4[(k4 * 4 + 3) * 32 + lane];
        #pragma unroll
        for (int r = 0; r < 8; r++) {
            float4 a = As4[(rbase + r) * 32 + k4];
            acc[r].x = fmaf(a.x, w0.x, acc[r].x); acc[r].y = fmaf(a.x, w0.y, acc[r].y);
            acc[r].z = fmaf(a.x, w0.z, acc[r].z); acc[r].w = fmaf(a.x, w0.w, acc[r].w);
            acc[r].x = fmaf(a.y, w1.x, acc[r].x); acc[r].y = fmaf(a.y, w1.y, acc[r].y);
            acc[r].z = fmaf(a.y, w1.z, acc[r].z); acc[r].w = fmaf(a.y, w1.w, acc[r].w);
            acc[r].x = fmaf(a.z, w2.x, acc[r].x); acc[r].y = fmaf(a.z, w2.y, acc[r].y);
            acc[r].z = fmaf(a.z, w2.z, acc[r].z); acc[r].w = fmaf(a.z, w2.w, acc[r].w);
            acc[r].x = fmaf(a.w, w3.x, acc[r].x); acc[r].y = fmaf(a.w, w3.y, acc[r].y);
            acc[r].z = fmaf(a.w, w3.z, acc[r].z); acc[r].w = fmaf(a.w, w3.w, acc[r].w);
        }
    }

    float4* O4 = (float4*)g_lin;
    #pragma unroll
    for (int r = 0; r < 8; r++) {
        int row = row0 + rbase + r;
        if (row < M) {
            float dv = g_dinv[row];
            float4 o;
            o.x = acc[r].x * dv; o.y = acc[r].y * dv;
            o.z = acc[r].z * dv; o.w = acc[r].w * dv;
            O4[(size_t)row * 32 + lane] = o;
        }
    }
}

// ---------------------------------------------------------------- aggregate: agg[d] = b + dinv[d]*(lin'[d] + sum lin'[s])
// Uniform (broadcast) index loads, no shuffles; unroll-4 for MLP.
__global__ void k_aggregate(const float* __restrict__ b, int n) {
    int gwarp = (blockIdx.x * blockDim.x + threadIdx.x) >> 5;
    int lane  = threadIdx.x & 31;
    if (gwarp >= n) return;

    const float4* lin4 = (const float4*)g_lin;
    float4 acc = lin4[(size_t)gwarp * 32 + lane];   // self term (already dinv-scaled)

    int beg = g_rowptr[gwarp];
    int end = g_rowptr[gwarp + 1];
    int j = beg;
    for (; j + 4 <= end; j += 4) {
        int s0 = g_csrsrc[j];
        int s1 = g_csrsrc[j + 1];
        int s2 = g_csrsrc[j + 2];
        int s3 = g_csrsrc[j + 3];
        float4 v0 = lin4[(size_t)s0 * 32 + lane];
        float4 v1 = lin4[(size_t)s1 * 32 + lane];
        float4 v2 = lin4[(size_t)s2 * 32 + lane];
        float4 v3 = lin4[(size_t)s3 * 32 + lane];
        acc.x += v0.x + v1.x + v2.x + v3.x;
        acc.y += v0.y + v1.y + v2.y + v3.y;
        acc.z += v0.z + v1.z + v2.z + v3.z;
        acc.w += v0.w + v1.w + v2.w + v3.w;
    }
    for (; j < end; j++) {
        int s = g_csrsrc[j];
        float4 v = lin4[(size_t)s * 32 + lane];
        acc.x += v.x; acc.y += v.y; acc.z += v.z; acc.w += v.w;
    }

    float di = g_dinv[gwarp];
    float4 bb = ((const float4*)b)[lane];
    float4 o;
    o.x = fmaf(acc.x, di, bb.x);
    o.y = fmaf(acc.y, di, bb.y);
    o.z = fmaf(acc.z, di, bb.z);
    o.w = fmaf(acc.w, di, bb.w);
    ((float4*)g_agg)[(size_t)gwarp * 32 + lane] = o;
}

// ---------------------------------------------------------------- node projection as blocked GEMM:
// P[n, 32] = relu(g_agg[n,128]) @ Wp[128,32], Wp packed from Wfc rows 0..255.
#define PROJ_BM 64
__global__ void k_proj(const float* __restrict__ Wfc, int n) {
    __shared__ float Ws[128 * 32];        // Ws[k*32 + l]
    __shared__ float As[PROJ_BM * 128];   // 32 KB

    int tid = threadIdx.x;
    for (int idx = tid; idx < 128 * 32; idx += 256) {
        int k = idx >> 5, l = idx & 31;
        Ws[idx] = (l < 16) ? Wfc[k * 16 + l] : Wfc[(128 + k) * 16 + (l - 16)];
    }

    int row0 = blockIdx.x * PROJ_BM;
    float4* As4 = (float4*)As;
    const float4* A4 = (const float4*)g_agg;
    #pragma unroll
    for (int i = 0; i < 8; i++) {
        int idx = tid + i * 256;          // 0..2047
        int r   = idx >> 5;
        float4 v = make_float4(0.f, 0.f, 0.f, 0.f);
        if (row0 + r < n) {
            v = A4[(size_t)(row0 + r) * 32 + (idx & 31)];
            v.x = fmaxf(v.x, 0.f); v.y = fmaxf(v.y, 0.f);
            v.z = fmaxf(v.z, 0.f); v.w = fmaxf(v.w, 0.f);
        }
        As4[idx] = v;
    }
    __syncthreads();

    int warp = tid >> 5, lane = tid & 31;
    int rbase = warp * 8;

    float acc[8];
    #pragma unroll
    for (int r = 0; r < 8; r++) acc[r] = 0.f;

    #pragma unroll 4
    for (int k4 = 0; k4 < 32; k4++) {
        float w0 = Ws[(k4 * 4 + 0) * 32 + lane];
        float w1 = Ws[(k4 * 4 + 1) * 32 + lane];
        float w2 = Ws[(k4 * 4 + 2) * 32 + lane];
        float w3 = Ws[(k4 * 4 + 3) * 32 + lane];
        #pragma unroll
        for (int r = 0; r < 8; r++) {
            float4 a = As4[(rbase + r) * 32 + k4];
            acc[r] = fmaf(a.x, w0, acc[r]);
            acc[r] = fmaf(a.y, w1, acc[r]);
            acc[r] = fmaf(a.z, w2, acc[r]);
            acc[r] = fmaf(a.w, w3, acc[r]);
        }
    }

    #pragma unroll
    for (int r = 0; r < 8; r++) {
        int row = row0 + rbase + r;
        if (row < n) g_P[(size_t)row * 32 + lane] = acc[r];
    }
}

// ---------------------------------------------------------------- edge output: out = logsoftmax(P_src[s] + P_dst[d] + ea@We + b)
#define EB 16   // edges per block (256 threads = 16 edges x 16 classes)
__global__ void k_edge2(const int* __restrict__ src, const int* __restrict__ dst,
                        const float* __restrict__ eattr,
                        const float* __restrict__ Wfc, const float* __restrict__ bfc,
                        float* __restrict__ out, int e) {
    __shared__ float We[32 * 16];    // Wfc rows 256..287
    __shared__ float bs[CDIM];
    __shared__ float ea[EB][33];     // padded to kill bank conflicts

    int tid = threadIdx.x;
    for (int i = tid; i < 32 * 16; i += 256) We[i] = Wfc[256 * 16 + i];
    if (tid < CDIM) bs[tid] = bfc[tid];

    int e0 = blockIdx.x * EB;
    if (tid < 128) {
        int el = tid >> 3, q = tid & 7;
        if (e0 + el < e) {
            float4 v = ((const float4*)(eattr + (size_t)(e0 + el) * 32))[q];
            ea[el][q * 4 + 0] = v.x; ea[el][q * 4 + 1] = v.y;
            ea[el][q * 4 + 2] = v.z; ea[el][q * 4 + 3] = v.w;
        }
    }
    __syncthreads();

    int el = tid >> 4, c = tid & 15;
    int edge = e0 + el;
    bool valid = edge < e;
    int ce = valid ? edge : e - 1;

    int s = src[ce], d = dst[ce];
    float acc = bs[c] + g_P[(size_t)s * 32 + c] + g_P[(size_t)d * 32 + 16 + c];
    #pragma unroll
    for (int k = 0; k < 32; k++)
        acc = fmaf(ea[el][k], We[k * 16 + c], acc);

    float m = acc;
    #pragma unroll
    for (int off = 8; off; off >>= 1)
        m = fmaxf(m, __shfl_xor_sync(0xffffffffu, m, off));
    float ex = __expf(acc - m);
    float ss = ex;
    #pragma unroll
    for (int off = 8; off; off >>= 1)
        ss += __shfl_xor_sync(0xffffffffu, ss, off);
    float res = acc - m - __logf(ss);
    if (valid) out[(size_t)edge * CDIM + c] = res;
}

// ---------------------------------------------------------------- launch
extern "C" void kernel_launch(void* const* d_in, const int* in_sizes, int n_in,
                              void* d_out, int out_size) {
    const float* x     = (const float*)d_in[0];
    const int*   ei    = (const int*)  d_in[1];
    const float* eattr = (const float*)d_in[2];
    const float* W1 = (const float*)d_in[3];  const float* b1 = (const float*)d_in[4];
    const float* W2 = (const float*)d_in[5];  const float* b2 = (const float*)d_in[6];
    const float* W3 = (const float*)d_in[7];  const float* b3 = (const float*)d_in[8];
    const float* Wfc = (const float*)d_in[9]; const float* bfc = (const float*)d_in[10];
    float* out = (float*)d_out;

    int n = in_sizes[0] / HDIM;
    int e = in_sizes[1] / 2;
    const int* src = ei;
    const int* dst = ei + e;

    cudaFuncSetAttribute(k_gemm128, cudaFuncAttributeMaxDynamicSharedMemorySize, GEMM_SMEM);

    int bn   = (n + 255) / 256;
    int be   = (e + 255) / 256;
    int bgem = (n + GEMM_BM - 1) / GEMM_BM;
    int bagg = (n + 7) / 8;
    int bedg = (e + EB - 1) / EB;
    int nscan = (n + SCAN_B - 1) / SCAN_B;

    // ---- CSR build (once; reused by all 3 layers) + degree norm
    k_cnt_zero<<<bn, 256>>>(n);
    k_hist    <<<be, 256>>>(dst, e);
    k_scan1   <<<nscan, SCAN_B>>>(n);
    k_scan2   <<<1, 128>>>(nscan);
    k_scan3   <<<nscan, SCAN_B>>>(n, e);
    k_fill    <<<be, 256>>>(src, dst, e);

    // ---- 3 GCN layers (lin' pre-scaled by dinv in GEMM epilogue)
    k_gemm128  <<<bgem, 256, GEMM_SMEM>>>(x, W1, n, 0);
    k_aggregate<<<bagg, 256>>>(b1, n);

    k_gemm128  <<<bgem, 256, GEMM_SMEM>>>(nullptr, W2, n, 1);
    k_aggregate<<<bagg, 256>>>(b2, n);

    k_gemm128  <<<bgem, 256, GEMM_SMEM>>>(nullptr, W3, n, 1);
    k_aggregate<<<bagg, 256>>>(b3, n);

    // ---- factored edge classifier
    k_proj <<<(n + PROJ_BM - 1) / PROJ_BM, 256>>>(Wfc, n);
    k_edge2<<<bedg, 256>>>(src, dst, eattr, Wfc, bfc, out, e);
}

// round 8
// speedup vs baseline: 1.1990x; 1.0376x over previous
#include <cuda_runtime.h>
#include <cuda_fp16.h>
#include <math.h>

#define HDIM   128
#define NMAX   100000
#define EMAX   1000000
#define CDIM   16
#define SCAN_B 1024

// Scratch (static device globals — allocation-free per harness rules)
__device__ float  g_dinv[NMAX];
__device__ __half g_lin[(size_t)NMAX * HDIM];  // lin' = dinv[row]*(act(A)@W), fp16
__device__ float  g_agg[(size_t)NMAX * HDIM];
__device__ float  g_P  [(size_t)NMAX * 32];    // per-node [P_src(16) | P_dst(16)]
__device__ int    g_cnt[NMAX];
__device__ int    g_rowptr[NMAX + 1];
__device__ int    g_cursor[NMAX];
__device__ int    g_csrsrc[EMAX];
__device__ int    g_blocksum[128];
__device__ int    g_blockoff[128];

// ---------------------------------------------------------------- CSR build
__global__ void k_cnt_zero(int n) {
    int i = blockIdx.x * blockDim.x + threadIdx.x;
    if (i < n) g_cnt[i] = 0;
}
__global__ void k_hist(const int* __restrict__ dst, int e) {
    int i = blockIdx.x * blockDim.x + threadIdx.x;
    if (i < e) atomicAdd(&g_cnt[dst[i]], 1);
}
__global__ void k_scan1(int n) {
    __shared__ int sm[SCAN_B];
    int i = blockIdx.x * SCAN_B + threadIdx.x;
    int v = (i < n) ? g_cnt[i] : 0;
    if (i < n) g_dinv[i] = rsqrtf((float)v + 1.0f);   // +1 self-loop
    sm[threadIdx.x] = v;
    __syncthreads();
    #pragma unroll
    for (int off = 1; off < SCAN_B; off <<= 1) {
        int t = (threadIdx.x >= off) ? sm[threadIdx.x - off] : 0;
        __syncthreads();
        sm[threadIdx.x] += t;
        __syncthreads();
    }
    if (i < n) g_rowptr[i] = sm[threadIdx.x] - v;     // exclusive
    if (threadIdx.x == SCAN_B - 1) g_blocksum[blockIdx.x] = sm[SCAN_B - 1];
}
__global__ void k_scan2(int nb) {
    __shared__ int sm[128];
    int t = threadIdx.x;
    int v = (t < nb) ? g_blocksum[t] : 0;
    sm[t] = v;
    __syncthreads();
    #pragma unroll
    for (int off = 1; off < 128; off <<= 1) {
        int x = (t >= off) ? sm[t - off] : 0;
        __syncthreads();
        sm[t] += x;
        __syncthreads();
    }
    if (t < nb) g_blockoff[t] = sm[t] - v;            // exclusive
}
__global__ void k_scan3(int n, int e) {
    int i = blockIdx.x * SCAN_B + threadIdx.x;
    if (i < n) {
        int r = g_rowptr[i] + g_blockoff[blockIdx.x];
        g_rowptr[i] = r;
        g_cursor[i] = r;
    }
    if (i == 0) g_rowptr[n] = e;
}
__global__ void k_fill(const int* __restrict__ src, const int* __restrict__ dst, int e) {
    int i = blockIdx.x * blockDim.x + threadIdx.x;
    if (i < e) {
        int pos = atomicAdd(&g_cursor[dst[i]], 1);
        g_csrsrc[pos] = src[i];
    }
}

// ---------------------------------------------------------------- GEMM: lin' = fp16( dinv[row] * (act(A) @ W) )
// Round-5 proven config: BM=64, 96 KB smem (2 CTAs/SM), 8 rows x 4 cols/thread.
#define GEMM_BM 64
#define GEMM_SMEM ((128*128 + GEMM_BM*128) * 4)
__global__ void k_gemm128(const float* __restrict__ Aext,
                          const float* __restrict__ W, int M, int relu) {
    extern __shared__ float sm[];
    float*  Ws  = sm;                 // 128*128
    float*  As  = sm + 128 * 128;     // BM*128
    float4* Ws4 = (float4*)Ws;
    float4* As4 = (float4*)As;

    const float* A = Aext ? Aext : g_agg;
    int tid = threadIdx.x;

    const float4* W4 = (const float4*)W;
    #pragma unroll
    for (int i = 0; i < 16; i++) Ws4[tid + i * 256] = W4[tid + i * 256];

    int row0 = blockIdx.x * GEMM_BM;
    const float4* A4 = (const float4*)A;
    #pragma unroll
    for (int i = 0; i < 8; i++) {
        int idx = tid + i * 256;       // 0..2047
        int r   = idx >> 5;
        float4 v = make_float4(0.f, 0.f, 0.f, 0.f);
        if (row0 + r < M) {
            v = A4[(size_t)(row0 + r) * 32 + (idx & 31)];
            if (relu) {
                v.x = fmaxf(v.x, 0.f); v.y = fmaxf(v.y, 0.f);
                v.z = fmaxf(v.z, 0.f); v.w = fmaxf(v.w, 0.f);
            }
        }
        As4[idx] = v;
    }
    __syncthreads();

    int warp = tid >> 5, lane = tid & 31;
    int rbase = warp * 8;

    float4 acc[8];
    #pragma unroll
    for (int r = 0; r < 8; r++) acc[r] = make_float4(0.f, 0.f, 0.f, 0.f);

    #pragma unroll 4
    for (int k4 = 0; k4 < 32; k4++) {
        float4 w0 = Ws4[(k4 * 4 + 0) * 32 + lane];
        float4 w1 = Ws4[(k4 * 4 + 1) * 32 + lane];
        float4 w2 = Ws4[(k4 * 4 + 2) * 32 + lane];
        float4 w3 = Ws4[(k4 * 4 + 3) * 32 + lane];
        #pragma unroll
        for (int r = 0; r < 8; r++) {
            float4 a = As4[(rbase + r) * 32 + k4];
            acc[r].x = fmaf(a.x, w0.x, acc[r].x); acc[r].y = fmaf(a.x, w0.y, acc[r].y);
            acc[r].z = fmaf(a.x, w0.z, acc[r].z); acc[r].w = fmaf(a.x, w0.w, acc[r].w);
            acc[r].x = fmaf(a.y, w1.x, acc[r].x); acc[r].y = fmaf(a.y, w1.y, acc[r].y);
            acc[r].z = fmaf(a.y, w1.z, acc[r].z); acc[r].w = fmaf(a.y, w1.w, acc[r].w);
            acc[r].x = fmaf(a.z, w2.x, acc[r].x); acc[r].y = fmaf(a.z, w2.y, acc[r].y);
            acc[r].z = fmaf(a.z, w2.z, acc[r].z); acc[r].w = fmaf(a.z, w2.w, acc[r].w);
            acc[r].x = fmaf(a.w, w3.x, acc[r].x); acc[r].y = fmaf(a.w, w3.y, acc[r].y);
            acc[r].z = fmaf(a.w, w3.z, acc[r].z); acc[r].w = fmaf(a.w, w3.w, acc[r].w);
        }
    }

    // epilogue: scale by dinv, convert to fp16, store 4 halves (8B) per lane
    uint2* O2 = (uint2*)g_lin;
    #pragma unroll
    for (int r = 0; r < 8; r++) {
        int row = row0 + rbase + r;
        if (row < M) {
            float dv = g_dinv[row];
            __half2 h0 = __floats2half2_rn(acc[r].x * dv, acc[r].y * dv);
            __half2 h1 = __floats2half2_rn(acc[r].z * dv, acc[r].w * dv);
            uint2 o;
            o.x = *(unsigned int*)&h0;
            o.y = *(unsigned int*)&h1;
            O2[(size_t)row * 32 + lane] = o;
        }
    }
}

// ---------------------------------------------------------------- aggregate: agg[d] = b + dinv[d]*(lin'[d] + sum lin'[s])
// fp16 gather (256B/row), fp32 accumulate. Uniform index loads, unroll-4 MLP.
__device__ __forceinline__ void acc_half4(float4& acc, uint2 raw) {
    __half2 h0 = *(__half2*)&raw.x;
    __half2 h1 = *(__half2*)&raw.y;
    float2 f0 = __half22float2(h0);
    float2 f1 = __half22float2(h1);
    acc.x += f0.x; acc.y += f0.y; acc.z += f1.x; acc.w += f1.y;
}
__global__ void k_aggregate(const float* __restrict__ b, int n) {
    int gwarp = (blockIdx.x * blockDim.x + threadIdx.x) >> 5;
    int lane  = threadIdx.x & 31;
    if (gwarp >= n) return;

    const uint2* lin2 = (const uint2*)g_lin;

    float4 acc = make_float4(0.f, 0.f, 0.f, 0.f);
    acc_half4(acc, lin2[(size_t)gwarp * 32 + lane]);   // self term (pre-scaled)

    int beg = g_rowptr[gwarp];
    int end = g_rowptr[gwarp + 1];
    int j = beg;
    for (; j + 4 <= end; j += 4) {
        int s0 = g_csrsrc[j];
        int s1 = g_csrsrc[j + 1];
        int s2 = g_csrsrc[j + 2];
        int s3 = g_csrsrc[j + 3];
        uint2 r0 = lin2[(size_t)s0 * 32 + lane];
        uint2 r1 = lin2[(size_t)s1 * 32 + lane];
        uint2 r2 = lin2[(size_t)s2 * 32 + lane];
        uint2 r3 = lin2[(size_t)s3 * 32 + lane];
        acc_half4(acc, r0);
        acc_half4(acc, r1);
        acc_half4(acc, r2);
        acc_half4(acc, r3);
    }
    for (; j < end; j++) {
        int s = g_csrsrc[j];
        acc_half4(acc, lin2[(size_t)s * 32 + lane]);
    }

    float di = g_dinv[gwarp];
    float4 bb = ((const float4*)b)[lane];
    float4 o;
    o.x = fmaf(acc.x, di, bb.x);
    o.y = fmaf(acc.y, di, bb.y);
    o.z = fmaf(acc.z, di, bb.z);
    o.w = fmaf(acc.w, di, bb.w);
    ((float4*)g_agg)[(size_t)gwarp * 32 + lane] = o;
}

// ---------------------------------------------------------------- node projection as blocked GEMM:
// P[n, 32] = relu(g_agg[n,128]) @ Wp[128,32], Wp packed from Wfc rows 0..255.
#define PROJ_BM 64
__global__ void k_proj(const float* __restrict__ Wfc, int n) {
    __shared__ float Ws[128 * 32];        // Ws[k*32 + l]
    __shared__ float As[PROJ_BM * 128];   // 32 KB

    int tid = threadIdx.x;
    for (int idx = tid; idx < 128 * 32; idx += 256) {
        int k = idx >> 5, l = idx & 31;
        Ws[idx] = (l < 16) ? Wfc[k * 16 + l] : Wfc[(128 + k) * 16 + (l - 16)];
    }

    int row0 = blockIdx.x * PROJ_BM;
    float4* As4 = (float4*)As;
    const float4* A4 = (const float4*)g_agg;
    #pragma unroll
    for (int i = 0; i < 8; i++) {
        int idx = tid + i * 256;          // 0..2047
        int r   = idx >> 5;
        float4 v = make_float4(0.f, 0.f, 0.f, 0.f);
        if (row0 + r < n) {
            v = A4[(size_t)(row0 + r) * 32 + (idx & 31)];
            v.x = fmaxf(v.x, 0.f); v.y = fmaxf(v.y, 0.f);
            v.z = fmaxf(v.z, 0.f); v.w = fmaxf(v.w, 0.f);
        }
        As4[idx] = v;
    }
    __syncthreads();

    int warp = tid >> 5, lane = tid & 31;
    int rbase = warp * 8;

    float acc[8];
    #pragma unroll
    for (int r = 0; r < 8; r++) acc[r] = 0.f;

    #pragma unroll 4
    for (int k4 = 0; k4 < 32; k4++) {
        float w0 = Ws[(k4 * 4 + 0) * 32 + lane];
        float w1 = Ws[(k4 * 4 + 1) * 32 + lane];
        float w2 = Ws[(k4 * 4 + 2) * 32 + lane];
        float w3 = Ws[(k4 * 4 + 3) * 32 + lane];
        #pragma unroll
        for (int r = 0; r < 8; r++) {
            float4 a = As4[(rbase + r) * 32 + k4];
            acc[r] = fmaf(a.x, w0, acc[r]);
            acc[r] = fmaf(a.y, w1, acc[r]);
            acc[r] = fmaf(a.z, w2, acc[r]);
            acc[r] = fmaf(a.w, w3, acc[r]);
        }
    }

    #pragma unroll
    for (int r = 0; r < 8; r++) {
        int row = row0 + rbase + r;
        if (row < n) g_P[(size_t)row * 32 + lane] = acc[r];
    }
}

// ---------------------------------------------------------------- edge output: out = logsoftmax(P_src[s] + P_dst[d] + ea@We + b)
#define EB 16   // edges per block (256 threads = 16 edges x 16 classes)
__global__ void k_edge2(const int* __restrict__ src, const int* __restrict__ dst,
                        const float* __restrict__ eattr,
                        const float* __restrict__ Wfc, const float* __restrict__ bfc,
                        float* __restrict__ out, int e) {
    __shared__ float We[32 * 16];    // Wfc rows 256..287
    __shared__ float bs[CDIM];
    __shared__ float ea[EB][33];     // padded to kill bank conflicts

    int tid = threadIdx.x;
    for (int i = tid; i < 32 * 16; i += 256) We[i] = Wfc[256 * 16 + i];
    if (tid < CDIM) bs[tid] = bfc[tid];

    int e0 = blockIdx.x * EB;
    if (tid < 128) {
        int el = tid >> 3, q = tid & 7;
        if (e0 + el < e) {
            float4 v = ((const float4*)(eattr + (size_t)(e0 + el) * 32))[q];
            ea[el][q * 4 + 0] = v.x; ea[el][q * 4 + 1] = v.y;
            ea[el][q * 4 + 2] = v.z; ea[el][q * 4 + 3] = v.w;
        }
    }
    __syncthreads();

    int el = tid >> 4, c = tid & 15;
    int edge = e0 + el;
    bool valid = edge < e;
    int ce = valid ? edge : e - 1;

    int s = src[ce], d = dst[ce];
    float acc = bs[c] + g_P[(size_t)s * 32 + c] + g_P[(size_t)d * 32 + 16 + c];
    #pragma unroll
    for (int k = 0; k < 32; k++)
        acc = fmaf(ea[el][k], We[k * 16 + c], acc);

    float m = acc;
    #pragma unroll
    for (int off = 8; off; off >>= 1)
        m = fmaxf(m, __shfl_xor_sync(0xffffffffu, m, off));
    float ex = __expf(acc - m);
    float ss = ex;
    #pragma unroll
    for (int off = 8; off; off >>= 1)
        ss += __shfl_xor_sync(0xffffffffu, ss, off);
    float res = acc - m - __logf(ss);
    if (valid) out[(size_t)edge * CDIM + c] = res;
}

// ---------------------------------------------------------------- launch
extern "C" void kernel_launch(void* const* d_in, const int* in_sizes, int n_in,
                              void* d_out, int out_size) {
    const float* x     = (const float*)d_in[0];
    const int*   ei    = (const int*)  d_in[1];
    const float* eattr = (const float*)d_in[2];
    const float* W1 = (const float*)d_in[3];  const float* b1 = (const float*)d_in[4];
    const float* W2 = (const float*)d_in[5];  const float* b2 = (const float*)d_in[6];
    const float* W3 = (const float*)d_in[7];  const float* b3 = (const float*)d_in[8];
    const float* Wfc = (const float*)d_in[9]; const float* bfc = (const float*)d_in[10];
    float* out = (float*)d_out;

    int n = in_sizes[0] / HDIM;
    int e = in_sizes[1] / 2;
    const int* src = ei;
    const int* dst = ei + e;

    cudaFuncSetAttribute(k_gemm128, cudaFuncAttributeMaxDynamicSharedMemorySize, GEMM_SMEM);

    int bn   = (n + 255) / 256;
    int be   = (e + 255) / 256;
    int bgem = (n + GEMM_BM - 1) / GEMM_BM;
    int bagg = (n + 7) / 8;
    int bedg = (e + EB - 1) / EB;
    int nscan = (n + SCAN_B - 1) / SCAN_B;

    // ---- CSR build (once; reused by all 3 layers) + degree norm
    k_cnt_zero<<<bn, 256>>>(n);
    k_hist    <<<be, 256>>>(dst, e);
    k_scan1   <<<nscan, SCAN_B>>>(n);
    k_scan2   <<<1, 128>>>(nscan);
    k_scan3   <<<nscan, SCAN_B>>>(n, e);
    k_fill    <<<be, 256>>>(src, dst, e);

    // ---- 3 GCN layers (lin' pre-scaled by dinv, stored fp16)
    k_gemm128  <<<bgem, 256, GEMM_SMEM>>>(x, W1, n, 0);
    k_aggregate<<<bagg, 256>>>(b1, n);

    k_gemm128  <<<bgem, 256, GEMM_SMEM>>>(nullptr, W2, n, 1);
    k_aggregate<<<bagg, 256>>>(b2, n);

    k_gemm128  <<<bgem, 256, GEMM_SMEM>>>(nullptr, W3, n, 1);
    k_aggregate<<<bagg, 256>>>(b3, n);

    // ---- factored edge classifier
    k_proj <<<(n + PROJ_BM - 1) / PROJ_BM, 256>>>(Wfc, n);
    k_edge2<<<bedg, 256>>>(src, dst, eattr, Wfc, bfc, out, e);
}

// round 9
// speedup vs baseline: 1.4635x; 1.2206x over previous
#include <cuda_runtime.h>
#include <cuda_fp16.h>
#include <mma.h>
#include <math.h>

using namespace nvcuda;

#define HDIM   128
#define NMAX   100000
#define EMAX   1000000
#define CDIM   16
#define SCAN_B 1024

// Scratch (static device globals — allocation-free per harness rules)
__device__ float  g_dinv[NMAX];
__device__ __half g_lin [(size_t)NMAX * HDIM];  // lin' = dinv[row]*(act(A)@W), fp16
__device__ float  g_agg [(size_t)NMAX * HDIM];  // pre-relu h (fp32, for proj)
__device__ __half g_aggh[(size_t)NMAX * HDIM];  // fp16 GEMM input: x, then relu(h)
__device__ __half g_Wh  [3][128 * 128];         // fp16 weights
__device__ float  g_P   [(size_t)NMAX * 32];    // per-node [P_src(16) | P_dst(16)]
__device__ int    g_cnt[NMAX];
__device__ int    g_rowptr[NMAX + 1];
__device__ int    g_cursor[NMAX];
__device__ int    g_csrsrc[EMAX];
__device__ int    g_blocksum[128];
__device__ int    g_blockoff[128];

// ---------------------------------------------------------------- fp32 -> fp16 conversion (vectorized)
__global__ void k_cvt_half(const float* __restrict__ src, __half* __restrict__ dst, int n4) {
    int i = blockIdx.x * blockDim.x + threadIdx.x;   // over float4 elements
    if (i >= n4) return;
    float4 v = ((const float4*)src)[i];
    __half2 h0 = __floats2half2_rn(v.x, v.y);
    __half2 h1 = __floats2half2_rn(v.z, v.w);
    uint2 o;
    o.x = *(unsigned int*)&h0;
    o.y = *(unsigned int*)&h1;
    ((uint2*)dst)[i] = o;
}

// ---------------------------------------------------------------- CSR build
__global__ void k_cnt_zero(int n) {
    int i = blockIdx.x * blockDim.x + threadIdx.x;
    if (i < n) g_cnt[i] = 0;
}
__global__ void k_hist(const int* __restrict__ dst, int e) {
    int i = blockIdx.x * blockDim.x + threadIdx.x;
    if (i < e) atomicAdd(&g_cnt[dst[i]], 1);
}
__global__ void k_scan1(int n) {
    __shared__ int sm[SCAN_B];
    int i = blockIdx.x * SCAN_B + threadIdx.x;
    int v = (i < n) ? g_cnt[i] : 0;
    if (i < n) g_dinv[i] = rsqrtf((float)v + 1.0f);   // +1 self-loop
    sm[threadIdx.x] = v;
    __syncthreads();
    #pragma unroll
    for (int off = 1; off < SCAN_B; off <<= 1) {
        int t = (threadIdx.x >= off) ? sm[threadIdx.x - off] : 0;
        __syncthreads();
        sm[threadIdx.x] += t;
        __syncthreads();
    }
    if (i < n) g_rowptr[i] = sm[threadIdx.x] - v;     // exclusive
    if (threadIdx.x == SCAN_B - 1) g_blocksum[blockIdx.x] = sm[SCAN_B - 1];
}
__global__ void k_scan2(int nb) {
    __shared__ int sm[128];
    int t = threadIdx.x;
    int v = (t < nb) ? g_blocksum[t] : 0;
    sm[t] = v;
    __syncthreads();
    #pragma unroll
    for (int off = 1; off < 128; off <<= 1) {
        int x = (t >= off) ? sm[t - off] : 0;
        __syncthreads();
        sm[t] += x;
        __syncthreads();
    }
    if (t < nb) g_blockoff[t] = sm[t] - v;            // exclusive
}
__global__ void k_scan3(int n, int e) {
    int i = blockIdx.x * SCAN_B + threadIdx.x;
    if (i < n) {
        int r = g_rowptr[i] + g_blockoff[blockIdx.x];
        g_rowptr[i] = r;
        g_cursor[i] = r;
    }
    if (i == 0) g_rowptr[n] = e;
}
__global__ void k_fill(const int* __restrict__ src, const int* __restrict__ dst, int e) {
    int i = blockIdx.x * blockDim.x + threadIdx.x;
    if (i < e) {
        int pos = atomicAdd(&g_cursor[dst[i]], 1);
        g_csrsrc[pos] = src[i];
    }
}

// ---------------------------------------------------------------- GEMM (tensor cores): lin' = fp16( dinv * (g_aggh @ Wh) )
// BM=128, 256 threads (8 warps). A,W fp16 smem-resident (LDA pad 136).
// Warp w: rows [w*16, w*16+16), 8 col fragments, K = 8 mma steps.
#define GW_LDA  136
#define GW_SMEM (2 * 128 * GW_LDA * 2)   // 69632 B (also covers 64KB fp32 staging)
__global__ void k_gemm_wmma(const __half* __restrict__ Wh, int M, int widx) {
    extern __shared__ char smraw[];
    __half* As = (__half*)smraw;                         // 128 x 136
    __half* Ws = (__half*)(smraw + 128 * GW_LDA * 2);    // 128 x 136

    int tid = threadIdx.x;
    int row0 = blockIdx.x * 128;

    // load W (16384 halves = 2048 uint4; 8 per thread)
    const uint4* W4 = (const uint4*)(g_Wh[widx]);
    #pragma unroll
    for (int i = 0; i < 8; i++) {
        int idx = tid + i * 256;
        int r = idx >> 4, c = (idx & 15) * 8;
        *(uint4*)(Ws + r * GW_LDA + c) = W4[idx];
    }
    // load A tile (128 rows x 128 halves), zero-pad OOB rows
    const uint4* A4 = (const uint4*)g_aggh;
    #pragma unroll
    for (int i = 0; i < 8; i++) {
        int idx = tid + i * 256;
        int r = idx >> 4, c = (idx & 15) * 8;
        uint4 v = make_uint4(0u, 0u, 0u, 0u);
        if (row0 + r < M) v = A4[(size_t)(row0 + r) * 16 + (idx & 15)];
        *(uint4*)(As + r * GW_LDA + c) = v;
    }
    __syncthreads();

    int warp = tid >> 5;

    wmma::fragment<wmma::accumulator, 16, 16, 16, float> acc[8];
    #pragma unroll
    for (int c = 0; c < 8; c++) wmma::fill_fragment(acc[c], 0.f);

    #pragma unroll
    for (int k = 0; k < 8; k++) {
        wmma::fragment<wmma::matrix_a, 16, 16, 16, __half, wmma::row_major> af;
        wmma::load_matrix_sync(af, As + warp * 16 * GW_LDA + k * 16, GW_LDA);
        #pragma unroll
        for (int c = 0; c < 8; c++) {
            wmma::fragment<wmma::matrix_b, 16, 16, 16, __half, wmma::row_major> bf;
            wmma::load_matrix_sync(bf, Ws + k * 16 * GW_LDA + c * 16, GW_LDA);
            wmma::mma_sync(acc[c], af, bf, acc[c]);
        }
    }
    __syncthreads();     // done reading As/Ws — reuse as fp32 staging

    float* Os = (float*)smraw;   // 128 x 128 fp32 (64 KB)
    #pragma unroll
    for (int c = 0; c < 8; c++)
        wmma::store_matrix_sync(Os + warp * 16 * 128 + c * 16, acc[c], 128, wmma::mem_row_major);
    __syncthreads();

    // epilogue: scale by dinv, pack fp16, store
    uint2* O2 = (uint2*)g_lin;
    #pragma unroll
    for (int i = 0; i < 16; i++) {
        int idx = tid + i * 256;            // 0..4095 over 128 rows x 32 float4
        int r = idx >> 5, c4 = idx & 31;
        int row = row0 + r;
        if (row < M) {
            float4 v = ((const float4*)Os)[idx];
            float dv = g_dinv[row];
            __half2 h0 = __floats2half2_rn(v.x * dv, v.y * dv);
            __half2 h1 = __floats2half2_rn(v.z * dv, v.w * dv);
            uint2 o;
            o.x = *(unsigned int*)&h0;
            o.y = *(unsigned int*)&h1;
            O2[(size_t)row * 32 + c4] = o;
        }
    }
}

// ---------------------------------------------------------------- aggregate: h[d] = b + dinv[d]*(lin'[d] + sum lin'[s])
// Writes fp32 g_agg (pre-relu) and fp16 g_aggh = relu(h) for next GEMM.
__device__ __forceinline__ void acc_half4(float4& acc, uint2 raw) {
    __half2 h0 = *(__half2*)&raw.x;
    __half2 h1 = *(__half2*)&raw.y;
    float2 f0 = __half22float2(h0);
    float2 f1 = __half22float2(h1);
    acc.x += f0.x; acc.y += f0.y; acc.z += f1.x; acc.w += f1.y;
}
__global__ void k_aggregate(const float* __restrict__ b, int n) {
    int gwarp = (blockIdx.x * blockDim.x + threadIdx.x) >> 5;
    int lane  = threadIdx.x & 31;
    if (gwarp >= n) return;

    const uint2* lin2 = (const uint2*)g_lin;

    float4 acc = make_float4(0.f, 0.f, 0.f, 0.f);
    acc_half4(acc, lin2[(size_t)gwarp * 32 + lane]);   // self term (pre-scaled)

    int beg = g_rowptr[gwarp];
    int end = g_rowptr[gwarp + 1];
    int j = beg;
    for (; j + 4 <= end; j += 4) {
        int s0 = g_csrsrc[j];
        int s1 = g_csrsrc[j + 1];
        int s2 = g_csrsrc[j + 2];
        int s3 = g_csrsrc[j + 3];
        uint2 r0 = lin2[(size_t)s0 * 32 + lane];
        uint2 r1 = lin2[(size_t)s1 * 32 + lane];
        uint2 r2 = lin2[(size_t)s2 * 32 + lane];
        uint2 r3 = lin2[(size_t)s3 * 32 + lane];
        acc_half4(acc, r0);
        acc_half4(acc, r1);
        acc_half4(acc, r2);
        acc_half4(acc, r3);
    }
    for (; j < end; j++) {
        int s = g_csrsrc[j];
        acc_half4(acc, lin2[(size_t)s * 32 + lane]);
    }

    float di = g_dinv[gwarp];
    float4 bb = ((const float4*)b)[lane];
    float4 o;
    o.x = fmaf(acc.x, di, bb.x);
    o.y = fmaf(acc.y, di, bb.y);
    o.z = fmaf(acc.z, di, bb.z);
    o.w = fmaf(acc.w, di, bb.w);
    ((float4*)g_agg)[(size_t)gwarp * 32 + lane] = o;

    // fp16 relu copy for next layer's GEMM input
    __half2 h0 = __floats2half2_rn(fmaxf(o.x, 0.f), fmaxf(o.y, 0.f));
    __half2 h1 = __floats2half2_rn(fmaxf(o.z, 0.f), fmaxf(o.w, 0.f));
    uint2 oh;
    oh.x = *(unsigned int*)&h0;
    oh.y = *(unsigned int*)&h1;
    ((uint2*)g_aggh)[(size_t)gwarp * 32 + lane] = oh;
}

// ---------------------------------------------------------------- node projection as blocked GEMM:
// P[n, 32] = relu(g_agg[n,128]) @ Wp[128,32], Wp packed from Wfc rows 0..255.
#define PROJ_BM 64
__global__ void k_proj(const float* __restrict__ Wfc, int n) {
    __shared__ float Ws[128 * 32];        // Ws[k*32 + l]
    __shared__ float As[PROJ_BM * 128];   // 32 KB

    int tid = threadIdx.x;
    for (int idx = tid; idx < 128 * 32; idx += 256) {
        int k = idx >> 5, l = idx & 31;
        Ws[idx] = (l < 16) ? Wfc[k * 16 + l] : Wfc[(128 + k) * 16 + (l - 16)];
    }

    int row0 = blockIdx.x * PROJ_BM;
    float4* As4 = (float4*)As;
    const float4* A4 = (const float4*)g_agg;
    #pragma unroll
    for (int i = 0; i < 8; i++) {
        int idx = tid + i * 256;          // 0..2047
        int r   = idx >> 5;
        float4 v = make_float4(0.f, 0.f, 0.f, 0.f);
        if (row0 + r < n) {
            v = A4[(size_t)(row0 + r) * 32 + (idx & 31)];
            v.x = fmaxf(v.x, 0.f); v.y = fmaxf(v.y, 0.f);
            v.z = fmaxf(v.z, 0.f); v.w = fmaxf(v.w, 0.f);
        }
        As4[idx] = v;
    }
    __syncthreads();

    int warp = tid >> 5, lane = tid & 31;
    int rbase = warp * 8;

    float acc[8];
    #pragma unroll
    for (int r = 0; r < 8; r++) acc[r] = 0.f;

    #pragma unroll 4
    for (int k4 = 0; k4 < 32; k4++) {
        float w0 = Ws[(k4 * 4 + 0) * 32 + lane];
        float w1 = Ws[(k4 * 4 + 1) * 32 + lane];
        float w2 = Ws[(k4 * 4 + 2) * 32 + lane];
        float w3 = Ws[(k4 * 4 + 3) * 32 + lane];
        #pragma unroll
        for (int r = 0; r < 8; r++) {
            float4 a = As4[(rbase + r) * 32 + k4];
            acc[r] = fmaf(a.x, w0, acc[r]);
            acc[r] = fmaf(a.y, w1, acc[r]);
            acc[r] = fmaf(a.z, w2, acc[r]);
            acc[r] = fmaf(a.w, w3, acc[r]);
        }
    }

    #pragma unroll
    for (int r = 0; r < 8; r++) {
        int row = row0 + rbase + r;
        if (row < n) g_P[(size_t)row * 32 + lane] = acc[r];
    }
}

// ---------------------------------------------------------------- edge output: out = logsoftmax(P_src[s] + P_dst[d] + ea@We + b)
#define EB 16   // edges per block (256 threads = 16 edges x 16 classes)
__global__ void k_edge2(const int* __restrict__ src, const int* __restrict__ dst,
                        const float* __restrict__ eattr,
                        const float* __restrict__ Wfc, const float* __restrict__ bfc,
                        float* __restrict__ out, int e) {
    __shared__ float We[32 * 16];    // Wfc rows 256..287
    __shared__ float bs[CDIM];
    __shared__ float ea[EB][33];     // padded to kill bank conflicts

    int tid = threadIdx.x;
    for (int i = tid; i < 32 * 16; i += 256) We[i] = Wfc[256 * 16 + i];
    if (tid < CDIM) bs[tid] = bfc[tid];

    int e0 = blockIdx.x * EB;
    if (tid < 128) {
        int el = tid >> 3, q = tid & 7;
        if (e0 + el < e) {
            float4 v = ((const float4*)(eattr + (size_t)(e0 + el) * 32))[q];
            ea[el][q * 4 + 0] = v.x; ea[el][q * 4 + 1] = v.y;
            ea[el][q * 4 + 2] = v.z; ea[el][q * 4 + 3] = v.w;
        }
    }
    __syncthreads();

    int el = tid >> 4, c = tid & 15;
    int edge = e0 + el;
    bool valid = edge < e;
    int ce = valid ? edge : e - 1;

    int s = src[ce], d = dst[ce];
    float acc = bs[c] + g_P[(size_t)s * 32 + c] + g_P[(size_t)d * 32 + 16 + c];
    #pragma unroll
    for (int k = 0; k < 32; k++)
        acc = fmaf(ea[el][k], We[k * 16 + c], acc);

    float m = acc;
    #pragma unroll
    for (int off = 8; off; off >>= 1)
        m = fmaxf(m, __shfl_xor_sync(0xffffffffu, m, off));
    float ex = __expf(acc - m);
    float ss = ex;
    #pragma unroll
    for (int off = 8; off; off >>= 1)
        ss += __shfl_xor_sync(0xffffffffu, ss, off);
    float res = acc - m - __logf(ss);
    if (valid) out[(size_t)edge * CDIM + c] = res;
}

// ---------------------------------------------------------------- launch
extern "C" void kernel_launch(void* const* d_in, const int* in_sizes, int n_in,
                              void* d_out, int out_size) {
    const float* x     = (const float*)d_in[0];
    const int*   ei    = (const int*)  d_in[1];
    const float* eattr = (const float*)d_in[2];
    const float* W1 = (const float*)d_in[3];  const float* b1 = (const float*)d_in[4];
    const float* W2 = (const float*)d_in[5];  const float* b2 = (const float*)d_in[6];
    const float* W3 = (const float*)d_in[7];  const float* b3 = (const float*)d_in[8];
    const float* Wfc = (const float*)d_in[9]; const float* bfc = (const float*)d_in[10];
    float* out = (float*)d_out;

    int n = in_sizes[0] / HDIM;
    int e = in_sizes[1] / 2;
    const int* src = ei;
    const int* dst = ei + e;

    cudaFuncSetAttribute(k_gemm_wmma, cudaFuncAttributeMaxDynamicSharedMemorySize, GW_SMEM);

    int bn   = (n + 255) / 256;
    int be   = (e + 255) / 256;
    int bgem = (n + 127) / 128;
    int bagg = (n + 7) / 8;
    int bedg = (e + EB - 1) / EB;
    int nscan = (n + SCAN_B - 1) / SCAN_B;

    // ---- fp16 conversions (weights + x) — independent of CSR build
    __half* wh_base;
    cudaGetSymbolAddress((void**)&wh_base, g_Wh);
    __half* aggh_base;
    cudaGetSymbolAddress((void**)&aggh_base, g_aggh);
    k_cvt_half<<<(128 * 32 + 255) / 256, 256>>>(W1, wh_base,               128 * 32);
    k_cvt_half<<<(128 * 32 + 255) / 256, 256>>>(W2, wh_base + 128 * 128,   128 * 32);
    k_cvt_half<<<(128 * 32 + 255) / 256, 256>>>(W3, wh_base + 2 * 128 * 128, 128 * 32);
    k_cvt_half<<<(n * 32 + 255) / 256, 256>>>(x, aggh_base, n * 32);

    // ---- CSR build (once; reused by all 3 layers) + degree norm
    k_cnt_zero<<<bn, 256>>>(n);
    k_hist    <<<be, 256>>>(dst, e);
    k_scan1   <<<nscan, SCAN_B>>>(n);
    k_scan2   <<<1, 128>>>(nscan);
    k_scan3   <<<nscan, SCAN_B>>>(n, e);
    k_fill    <<<be, 256>>>(src, dst, e);

    // ---- 3 GCN layers (tensor-core GEMM reads g_aggh; aggregate refreshes it)
    k_gemm_wmma<<<bgem, 256, GW_SMEM>>>(nullptr, n, 0);
    k_aggregate<<<bagg, 256>>>(b1, n);

    k_gemm_wmma<<<bgem, 256, GW_SMEM>>>(nullptr, n, 1);
    k_aggregate<<<bagg, 256>>>(b2, n);

    k_gemm_wmma<<<bgem, 256, GW_SMEM>>>(nullptr, n, 2);
    k_aggregate<<<bagg, 256>>>(b3, n);

    // ---- factored edge classifier
    k_proj <<<(n + PROJ_BM - 1) / PROJ_BM, 256>>>(Wfc, n);
    k_edge2<<<bedg, 256>>>(src, dst, eattr, Wfc, bfc, out, e);
}

// round 10
// speedup vs baseline: 1.5023x; 1.0265x over previous
#include <cuda_runtime.h>
#include <cuda_fp16.h>
#include <mma.h>
#include <math.h>

using namespace nvcuda;

#define HDIM   128
#define NMAX   100000
#define EMAX   1000000
#define CDIM   16
#define SCAN_B 1024

// Scratch (static device globals — allocation-free per harness rules)
__device__ float  g_dinv[NMAX];
__device__ __half g_lin [(size_t)NMAX * HDIM];  // lin' = dinv[row]*(act(A)@W), fp16
__device__ float  g_agg [(size_t)NMAX * HDIM];  // pre-relu h (fp32, for proj)
__device__ __half g_aggh[(size_t)NMAX * HDIM];  // fp16 GEMM input: x, then relu(h)
__device__ __half g_Wh  [3][128 * 128];         // fp16 weights
__device__ float  g_P   [(size_t)NMAX * 32];    // per-node [P_src(16) | P_dst(16)]
__device__ int    g_cnt[NMAX];
__device__ int    g_rowptr[NMAX + 1];
__device__ int    g_cursor[NMAX];
__device__ int    g_csrsrc[EMAX];
__device__ int    g_blocksum[128];
__device__ int    g_blockoff[128];

// ---------------------------------------------------------------- fp32 -> fp16 conversion (vectorized)
__global__ void k_cvt_half(const float* __restrict__ src, __half* __restrict__ dst, int n4) {
    int i = blockIdx.x * blockDim.x + threadIdx.x;   // over float4 elements
    if (i >= n4) return;
    float4 v = ((const float4*)src)[i];
    __half2 h0 = __floats2half2_rn(v.x, v.y);
    __half2 h1 = __floats2half2_rn(v.z, v.w);
    uint2 o;
    o.x = *(unsigned int*)&h0;
    o.y = *(unsigned int*)&h1;
    ((uint2*)dst)[i] = o;
}

// ---------------------------------------------------------------- CSR build
__global__ void k_cnt_zero(int n) {
    int i = blockIdx.x * blockDim.x + threadIdx.x;
    if (i < n) g_cnt[i] = 0;
}
__global__ void k_hist(const int* __restrict__ dst, int e) {
    int i = blockIdx.x * blockDim.x + threadIdx.x;
    if (i < e) atomicAdd(&g_cnt[dst[i]], 1);
}
__global__ void k_scan1(int n) {
    __shared__ int sm[SCAN_B];
    int i = blockIdx.x * SCAN_B + threadIdx.x;
    int v = (i < n) ? g_cnt[i] : 0;
    if (i < n) g_dinv[i] = rsqrtf((float)v + 1.0f);   // +1 self-loop
    sm[threadIdx.x] = v;
    __syncthreads();
    #pragma unroll
    for (int off = 1; off < SCAN_B; off <<= 1) {
        int t = (threadIdx.x >= off) ? sm[threadIdx.x - off] : 0;
        __syncthreads();
        sm[threadIdx.x] += t;
        __syncthreads();
    }
    if (i < n) g_rowptr[i] = sm[threadIdx.x] - v;     // exclusive
    if (threadIdx.x == SCAN_B - 1) g_blocksum[blockIdx.x] = sm[SCAN_B - 1];
}
__global__ void k_scan2(int nb) {
    __shared__ int sm[128];
    int t = threadIdx.x;
    int v = (t < nb) ? g_blocksum[t] : 0;
    sm[t] = v;
    __syncthreads();
    #pragma unroll
    for (int off = 1; off < 128; off <<= 1) {
        int x = (t >= off) ? sm[t - off] : 0;
        __syncthreads();
        sm[t] += x;
        __syncthreads();
    }
    if (t < nb) g_blockoff[t] = sm[t] - v;            // exclusive
}
__global__ void k_scan3(int n, int e) {
    int i = blockIdx.x * SCAN_B + threadIdx.x;
    if (i < n) {
        int r = g_rowptr[i] + g_blockoff[blockIdx.x];
        g_rowptr[i] = r;
        g_cursor[i] = r;
    }
    if (i == 0) g_rowptr[n] = e;
}
__global__ void k_fill(const int* __restrict__ src, const int* __restrict__ dst, int e) {
    int i = blockIdx.x * blockDim.x + threadIdx.x;
    if (i < e) {
        int pos = atomicAdd(&g_cursor[dst[i]], 1);
        g_csrsrc[pos] = src[i];
    }
}

// ---------------------------------------------------------------- GEMM (tensor cores): lin' = fp16( dinv * (g_aggh @ Wh) )
#define GW_LDA  136
#define GW_SMEM (2 * 128 * GW_LDA * 2)   // 69632 B (also covers 64KB fp32 staging)
__global__ void k_gemm_wmma(const __half* __restrict__ Wh, int M, int widx) {
    extern __shared__ char smraw[];
    __half* As = (__half*)smraw;                         // 128 x 136
    __half* Ws = (__half*)(smraw + 128 * GW_LDA * 2);    // 128 x 136

    int tid = threadIdx.x;
    int row0 = blockIdx.x * 128;

    const uint4* W4 = (const uint4*)(g_Wh[widx]);
    #pragma unroll
    for (int i = 0; i < 8; i++) {
        int idx = tid + i * 256;
        int r = idx >> 4, c = (idx & 15) * 8;
        *(uint4*)(Ws + r * GW_LDA + c) = W4[idx];
    }
    const uint4* A4 = (const uint4*)g_aggh;
    #pragma unroll
    for (int i = 0; i < 8; i++) {
        int idx = tid + i * 256;
        int r = idx >> 4, c = (idx & 15) * 8;
        uint4 v = make_uint4(0u, 0u, 0u, 0u);
        if (row0 + r < M) v = A4[(size_t)(row0 + r) * 16 + (idx & 15)];
        *(uint4*)(As + r * GW_LDA + c) = v;
    }
    __syncthreads();

    int warp = tid >> 5;

    wmma::fragment<wmma::accumulator, 16, 16, 16, float> acc[8];
    #pragma unroll
    for (int c = 0; c < 8; c++) wmma::fill_fragment(acc[c], 0.f);

    #pragma unroll
    for (int k = 0; k < 8; k++) {
        wmma::fragment<wmma::matrix_a, 16, 16, 16, __half, wmma::row_major> af;
        wmma::load_matrix_sync(af, As + warp * 16 * GW_LDA + k * 16, GW_LDA);
        #pragma unroll
        for (int c = 0; c < 8; c++) {
            wmma::fragment<wmma::matrix_b, 16, 16, 16, __half, wmma::row_major> bf;
            wmma::load_matrix_sync(bf, Ws + k * 16 * GW_LDA + c * 16, GW_LDA);
            wmma::mma_sync(acc[c], af, bf, acc[c]);
        }
    }
    __syncthreads();     // done reading As/Ws — reuse as fp32 staging

    float* Os = (float*)smraw;   // 128 x 128 fp32 (64 KB)
    #pragma unroll
    for (int c = 0; c < 8; c++)
        wmma::store_matrix_sync(Os + warp * 16 * 128 + c * 16, acc[c], 128, wmma::mem_row_major);
    __syncthreads();

    uint2* O2 = (uint2*)g_lin;
    #pragma unroll
    for (int i = 0; i < 16; i++) {
        int idx = tid + i * 256;            // 0..4095 over 128 rows x 32 float4
        int r = idx >> 5, c4 = idx & 31;
        int row = row0 + r;
        if (row < M) {
            float4 v = ((const float4*)Os)[idx];
            float dv = g_dinv[row];
            __half2 h0 = __floats2half2_rn(v.x * dv, v.y * dv);
            __half2 h1 = __floats2half2_rn(v.z * dv, v.w * dv);
            uint2 o;
            o.x = *(unsigned int*)&h0;
            o.y = *(unsigned int*)&h1;
            O2[(size_t)row * 32 + c4] = o;
        }
    }
}

// ---------------------------------------------------------------- aggregate: h[d] = b + dinv[d]*(lin'[d] + sum lin'[s])
// 16-lane group per node (2 nodes/warp): lane owns uint4 = 8 halves of the
// 256B fp16 row. Unroll-8 batches => up to 16 outstanding gathers per warp.
__device__ __forceinline__ void acc_half8(float* acc, uint4 raw) {
    __half2 h0 = *(__half2*)&raw.x;
    __half2 h1 = *(__half2*)&raw.y;
    __half2 h2 = *(__half2*)&raw.z;
    __half2 h3 = *(__half2*)&raw.w;
    float2 f0 = __half22float2(h0);
    float2 f1 = __half22float2(h1);
    float2 f2 = __half22float2(h2);
    float2 f3 = __half22float2(h3);
    acc[0] += f0.x; acc[1] += f0.y; acc[2] += f1.x; acc[3] += f1.y;
    acc[4] += f2.x; acc[5] += f2.y; acc[6] += f3.x; acc[7] += f3.y;
}
__global__ void k_aggregate(const float* __restrict__ b, int n) {
    int grp  = (blockIdx.x * blockDim.x + threadIdx.x) >> 4;   // node id
    int lane = threadIdx.x & 15;                               // 16B chunk
    if (grp >= n) return;

    const uint4* lin4 = (const uint4*)g_lin;   // row stride = 16 uint4

    float acc[8] = {0.f, 0.f, 0.f, 0.f, 0.f, 0.f, 0.f, 0.f};
    acc_half8(acc, lin4[(size_t)grp * 16 + lane]);   // self term (pre-scaled)

    int beg = g_rowptr[grp];
    int end = g_rowptr[grp + 1];
    int j = beg;
    for (; j + 8 <= end; j += 8) {
        int s0 = g_csrsrc[j];
        int s1 = g_csrsrc[j + 1];
        int s2 = g_csrsrc[j + 2];
        int s3 = g_csrsrc[j + 3];
        int s4 = g_csrsrc[j + 4];
        int s5 = g_csrsrc[j + 5];
        int s6 = g_csrsrc[j + 6];
        int s7 = g_csrsrc[j + 7];
        uint4 r0 = lin4[(size_t)s0 * 16 + lane];
        uint4 r1 = lin4[(size_t)s1 * 16 + lane];
        uint4 r2 = lin4[(size_t)s2 * 16 + lane];
        uint4 r3 = lin4[(size_t)s3 * 16 + lane];
        uint4 r4 = lin4[(size_t)s4 * 16 + lane];
        uint4 r5 = lin4[(size_t)s5 * 16 + lane];
        uint4 r6 = lin4[(size_t)s6 * 16 + lane];
        uint4 r7 = lin4[(size_t)s7 * 16 + lane];
        acc_half8(acc, r0); acc_half8(acc, r1);
        acc_half8(acc, r2); acc_half8(acc, r3);
        acc_half8(acc, r4); acc_half8(acc, r5);
        acc_half8(acc, r6); acc_half8(acc, r7);
    }
    for (; j + 2 <= end; j += 2) {
        int s0 = g_csrsrc[j];
        int s1 = g_csrsrc[j + 1];
        uint4 r0 = lin4[(size_t)s0 * 16 + lane];
        uint4 r1 = lin4[(size_t)s1 * 16 + lane];
        acc_half8(acc, r0); acc_half8(acc, r1);
    }
    if (j < end) {
        int s = g_csrsrc[j];
        acc_half8(acc, lin4[(size_t)s * 16 + lane]);
    }

    float di = g_dinv[grp];
    const float4* b4 = (const float4*)b;
    float4 bb0 = b4[lane * 2];
    float4 bb1 = b4[lane * 2 + 1];
    float4 o0, o1;
    o0.x = fmaf(acc[0], di, bb0.x);
    o0.y = fmaf(acc[1], di, bb0.y);
    o0.z = fmaf(acc[2], di, bb0.z);
    o0.w = fmaf(acc[3], di, bb0.w);
    o1.x = fmaf(acc[4], di, bb1.x);
    o1.y = fmaf(acc[5], di, bb1.y);
    o1.z = fmaf(acc[6], di, bb1.z);
    o1.w = fmaf(acc[7], di, bb1.w);
    float4* agg4 = (float4*)g_agg;
    agg4[(size_t)grp * 32 + lane * 2]     = o0;
    agg4[(size_t)grp * 32 + lane * 2 + 1] = o1;

    // fp16 relu copy for next layer's GEMM input
    __half2 h0 = __floats2half2_rn(fmaxf(o0.x, 0.f), fmaxf(o0.y, 0.f));
    __half2 h1 = __floats2half2_rn(fmaxf(o0.z, 0.f), fmaxf(o0.w, 0.f));
    __half2 h2 = __floats2half2_rn(fmaxf(o1.x, 0.f), fmaxf(o1.y, 0.f));
    __half2 h3 = __floats2half2_rn(fmaxf(o1.z, 0.f), fmaxf(o1.w, 0.f));
    uint4 oh;
    oh.x = *(unsigned int*)&h0;
    oh.y = *(unsigned int*)&h1;
    oh.z = *(unsigned int*)&h2;
    oh.w = *(unsigned int*)&h3;
    ((uint4*)g_aggh)[(size_t)grp * 16 + lane] = oh;
}

// ---------------------------------------------------------------- node projection as blocked GEMM:
// P[n, 32] = relu(g_agg[n,128]) @ Wp[128,32], Wp packed from Wfc rows 0..255.
#define PROJ_BM 64
__global__ void k_proj(const float* __restrict__ Wfc, int n) {
    __shared__ float Ws[128 * 32];        // Ws[k*32 + l]
    __shared__ float As[PROJ_BM * 128];   // 32 KB

    int tid = threadIdx.x;
    for (int idx = tid; idx < 128 * 32; idx += 256) {
        int k = idx >> 5, l = idx & 31;
        Ws[idx] = (l < 16) ? Wfc[k * 16 + l] : Wfc[(128 + k) * 16 + (l - 16)];
    }

    int row0 = blockIdx.x * PROJ_BM;
    float4* As4 = (float4*)As;
    const float4* A4 = (const float4*)g_agg;
    #pragma unroll
    for (int i = 0; i < 8; i++) {
        int idx = tid + i * 256;          // 0..2047
        int r   = idx >> 5;
        float4 v = make_float4(0.f, 0.f, 0.f, 0.f);
        if (row0 + r < n) {
            v = A4[(size_t)(row0 + r) * 32 + (idx & 31)];
            v.x = fmaxf(v.x, 0.f); v.y = fmaxf(v.y, 0.f);
            v.z = fmaxf(v.z, 0.f); v.w = fmaxf(v.w, 0.f);
        }
        As4[idx] = v;
    }
    __syncthreads();

    int warp = tid >> 5, lane = tid & 31;
    int rbase = warp * 8;

    float acc[8];
    #pragma unroll
    for (int r = 0; r < 8; r++) acc[r] = 0.f;

    #pragma unroll 4
    for (int k4 = 0; k4 < 32; k4++) {
        float w0 = Ws[(k4 * 4 + 0) * 32 + lane];
        float w1 = Ws[(k4 * 4 + 1) * 32 + lane];
        float w2 = Ws[(k4 * 4 + 2) * 32 + lane];
        float w3 = Ws[(k4 * 4 + 3) * 32 + lane];
        #pragma unroll
        for (int r = 0; r < 8; r++) {
            float4 a = As4[(rbase + r) * 32 + k4];
            acc[r] = fmaf(a.x, w0, acc[r]);
            acc[r] = fmaf(a.y, w1, acc[r]);
            acc[r] = fmaf(a.z, w2, acc[r]);
            acc[r] = fmaf(a.w, w3, acc[r]);
        }
    }

    #pragma unroll
    for (int r = 0; r < 8; r++) {
        int row = row0 + rbase + r;
        if (row < n) g_P[(size_t)row * 32 + lane] = acc[r];
    }
}

// ---------------------------------------------------------------- edge output: out = logsoftmax(P_src[s] + P_dst[d] + ea@We + b)
#define EB 16   // edges per block (256 threads = 16 edges x 16 classes)
__global__ void k_edge2(const int* __restrict__ src, const int* __restrict__ dst,
                        const float* __restrict__ eattr,
                        const float* __restrict__ Wfc, const float* __restrict__ bfc,
                        float* __restrict__ out, int e) {
    __shared__ float We[32 * 16];    // Wfc rows 256..287
    __shared__ float bs[CDIM];
    __shared__ float ea[EB][33];     // padded to kill bank conflicts

    int tid = threadIdx.x;
    for (int i = tid; i < 32 * 16; i += 256) We[i] = Wfc[256 * 16 + i];
    if (tid < CDIM) bs[tid] = bfc[tid];

    int e0 = blockIdx.x * EB;
    if (tid < 128) {
        int el = tid >> 3, q = tid & 7;
        if (e0 + el < e) {
            float4 v = ((const float4*)(eattr + (size_t)(e0 + el) * 32))[q];
            ea[el][q * 4 + 0] = v.x; ea[el][q * 4 + 1] = v.y;
            ea[el][q * 4 + 2] = v.z; ea[el][q * 4 + 3] = v.w;
        }
    }
    __syncthreads();

    int el = tid >> 4, c = tid & 15;
    int edge = e0 + el;
    bool valid = edge < e;
    int ce = valid ? edge : e - 1;

    int s = src[ce], d = dst[ce];
    float acc = bs[c] + g_P[(size_t)s * 32 + c] + g_P[(size_t)d * 32 + 16 + c];
    #pragma unroll
    for (int k = 0; k < 32; k++)
        acc = fmaf(ea[el][k], We[k * 16 + c], acc);

    float m = acc;
    #pragma unroll
    for (int off = 8; off; off >>= 1)
        m = fmaxf(m, __shfl_xor_sync(0xffffffffu, m, off));
    float ex = __expf(acc - m);
    float ss = ex;
    #pragma unroll
    for (int off = 8; off; off >>= 1)
        ss += __shfl_xor_sync(0xffffffffu, ss, off);
    float res = acc - m - __logf(ss);
    if (valid) out[(size_t)edge * CDIM + c] = res;
}

// ---------------------------------------------------------------- launch
extern "C" void kernel_launch(void* const* d_in, const int* in_sizes, int n_in,
                              void* d_out, int out_size) {
    const float* x     = (const float*)d_in[0];
    const int*   ei    = (const int*)  d_in[1];
    const float* eattr = (const float*)d_in[2];
    const float* W1 = (const float*)d_in[3];  const float* b1 = (const float*)d_in[4];
    const float* W2 = (const float*)d_in[5];  const float* b2 = (const float*)d_in[6];
    const float* W3 = (const float*)d_in[7];  const float* b3 = (const float*)d_in[8];
    const float* Wfc = (const float*)d_in[9]; const float* bfc = (const float*)d_in[10];
    float* out = (float*)d_out;

    int n = in_sizes[0] / HDIM;
    int e = in_sizes[1] / 2;
    const int* src = ei;
    const int* dst = ei + e;

    cudaFuncSetAttribute(k_gemm_wmma, cudaFuncAttributeMaxDynamicSharedMemorySize, GW_SMEM);

    int bn   = (n + 255) / 256;
    int be   = (e + 255) / 256;
    int bgem = (n + 127) / 128;
    int bagg = (n * 16 + 255) / 256;   // 16 lanes per node
    int bedg = (e + EB - 1) / EB;
    int nscan = (n + SCAN_B - 1) / SCAN_B;

    // ---- fp16 conversions (weights + x) — independent of CSR build
    __half* wh_base;
    cudaGetSymbolAddress((void**)&wh_base, g_Wh);
    __half* aggh_base;
    cudaGetSymbolAddress((void**)&aggh_base, g_aggh);
    k_cvt_half<<<(128 * 32 + 255) / 256, 256>>>(W1, wh_base,               128 * 32);
    k_cvt_half<<<(128 * 32 + 255) / 256, 256>>>(W2, wh_base + 128 * 128,   128 * 32);
    k_cvt_half<<<(128 * 32 + 255) / 256, 256>>>(W3, wh_base + 2 * 128 * 128, 128 * 32);
    k_cvt_half<<<(n * 32 + 255) / 256, 256>>>(x, aggh_base, n * 32);

    // ---- CSR build (once; reused by all 3 layers) + degree norm
    k_cnt_zero<<<bn, 256>>>(n);
    k_hist    <<<be, 256>>>(dst, e);
    k_scan1   <<<nscan, SCAN_B>>>(n);
    k_scan2   <<<1, 128>>>(nscan);
    k_scan3   <<<nscan, SCAN_B>>>(n, e);
    k_fill    <<<be, 256>>>(src, dst, e);

    // ---- 3 GCN layers (tensor-core GEMM reads g_aggh; aggregate refreshes it)
    k_gemm_wmma<<<bgem, 256, GW_SMEM>>>(nullptr, n, 0);
    k_aggregate<<<bagg, 256>>>(b1, n);

    k_gemm_wmma<<<bgem, 256, GW_SMEM>>>(nullptr, n, 1);
    k_aggregate<<<bagg, 256>>>(b2, n);

    k_gemm_wmma<<<bgem, 256, GW_SMEM>>>(nullptr, n, 2);
    k_aggregate<<<bagg, 256>>>(b3, n);

    // ---- factored edge classifier
    k_proj <<<(n + PROJ_BM - 1) / PROJ_BM, 256>>>(Wfc, n);
    k_edge2<<<bedg, 256>>>(src, dst, eattr, Wfc, bfc, out, e);
}

// round 11
// speedup vs baseline: 1.7696x; 1.1779x over previous
#include <cuda_runtime.h>
#include <cuda_fp16.h>
#include <mma.h>
#include <math.h>

using namespace nvcuda;

#define HDIM   128
#define NMAX   100000
#define EMAX   1000000
#define CDIM   16
#define SCAN_B 1024

// Scratch (static device globals — allocation-free per harness rules)
__device__ float  g_dinv[NMAX];
__device__ __half g_lin [(size_t)NMAX * HDIM];  // lin' = dinv[row]*(act(A)@W), fp16
__device__ float  g_agg [(size_t)NMAX * HDIM];  // pre-relu h (fp32, for proj)
__device__ __half g_aggh[(size_t)NMAX * HDIM];  // fp16 GEMM input: x, then relu(h)
__device__ __half g_Wh  [3][128 * 128];         // fp16 weights
__device__ float  g_P   [(size_t)NMAX * 32];    // per-node [P_src(16) | P_dst(16)]
__device__ __half g_Q   [(size_t)EMAX * CDIM];  // per-edge eattr @ We (fp16)
__device__ int    g_cnt[NMAX];
__device__ int    g_rowptr[NMAX + 1];
__device__ int    g_cursor[NMAX];
__device__ int    g_csrsrc[EMAX];
__device__ int    g_blocksum[128];
__device__ int    g_blockoff[128];

// ---------------------------------------------------------------- fp32 -> fp16 conversion (vectorized)
__global__ void k_cvt_half(const float* __restrict__ src, __half* __restrict__ dst, int n4) {
    int i = blockIdx.x * blockDim.x + threadIdx.x;   // over float4 elements
    if (i >= n4) return;
    float4 v = ((const float4*)src)[i];
    __half2 h0 = __floats2half2_rn(v.x, v.y);
    __half2 h1 = __floats2half2_rn(v.z, v.w);
    uint2 o;
    o.x = *(unsigned int*)&h0;
    o.y = *(unsigned int*)&h1;
    ((uint2*)dst)[i] = o;
}

// ---------------------------------------------------------------- CSR build
__global__ void k_cnt_zero(int n) {
    int i = blockIdx.x * blockDim.x + threadIdx.x;
    if (i < n) g_cnt[i] = 0;
}
__global__ void k_hist(const int* __restrict__ dst, int e) {
    int i = blockIdx.x * blockDim.x + threadIdx.x;
    if (i < e) atomicAdd(&g_cnt[dst[i]], 1);
}
__global__ void k_scan1(int n) {
    __shared__ int sm[SCAN_B];
    int i = blockIdx.x * SCAN_B + threadIdx.x;
    int v = (i < n) ? g_cnt[i] : 0;
    if (i < n) g_dinv[i] = rsqrtf((float)v + 1.0f);   // +1 self-loop
    sm[threadIdx.x] = v;
    __syncthreads();
    #pragma unroll
    for (int off = 1; off < SCAN_B; off <<= 1) {
        int t = (threadIdx.x >= off) ? sm[threadIdx.x - off] : 0;
        __syncthreads();
        sm[threadIdx.x] += t;
        __syncthreads();
    }
    if (i < n) g_rowptr[i] = sm[threadIdx.x] - v;     // exclusive
    if (threadIdx.x == SCAN_B - 1) g_blocksum[blockIdx.x] = sm[SCAN_B - 1];
}
__global__ void k_scan2(int nb) {
    __shared__ int sm[128];
    int t = threadIdx.x;
    int v = (t < nb) ? g_blocksum[t] : 0;
    sm[t] = v;
    __syncthreads();
    #pragma unroll
    for (int off = 1; off < 128; off <<= 1) {
        int x = (t >= off) ? sm[t - off] : 0;
        __syncthreads();
        sm[t] += x;
        __syncthreads();
    }
    if (t < nb) g_blockoff[t] = sm[t] - v;            // exclusive
}
__global__ void k_scan3(int n, int e) {
    int i = blockIdx.x * SCAN_B + threadIdx.x;
    if (i < n) {
        int r = g_rowptr[i] + g_blockoff[blockIdx.x];
        g_rowptr[i] = r;
        g_cursor[i] = r;
    }
    if (i == 0) g_rowptr[n] = e;
}
__global__ void k_fill(const int* __restrict__ src, const int* __restrict__ dst, int e) {
    int i = blockIdx.x * blockDim.x + threadIdx.x;
    if (i < e) {
        int pos = atomicAdd(&g_cursor[dst[i]], 1);
        g_csrsrc[pos] = src[i];
    }
}

// ---------------------------------------------------------------- GEMM (tensor cores): lin' = fp16( dinv * (g_aggh @ Wh) )
#define GW_LDA  136
#define GW_SMEM (2 * 128 * GW_LDA * 2)   // 69632 B (also covers 64KB fp32 staging)
__global__ void k_gemm_wmma(const __half* __restrict__ Wh, int M, int widx) {
    extern __shared__ char smraw[];
    __half* As = (__half*)smraw;                         // 128 x 136
    __half* Ws = (__half*)(smraw + 128 * GW_LDA * 2);    // 128 x 136

    int tid = threadIdx.x;
    int row0 = blockIdx.x * 128;

    const uint4* W4 = (const uint4*)(g_Wh[widx]);
    #pragma unroll
    for (int i = 0; i < 8; i++) {
        int idx = tid + i * 256;
        int r = idx >> 4, c = (idx & 15) * 8;
        *(uint4*)(Ws + r * GW_LDA + c) = W4[idx];
    }
    const uint4* A4 = (const uint4*)g_aggh;
    #pragma unroll
    for (int i = 0; i < 8; i++) {
        int idx = tid + i * 256;
        int r = idx >> 4, c = (idx & 15) * 8;
        uint4 v = make_uint4(0u, 0u, 0u, 0u);
        if (row0 + r < M) v = A4[(size_t)(row0 + r) * 16 + (idx & 15)];
        *(uint4*)(As + r * GW_LDA + c) = v;
    }
    __syncthreads();

    int warp = tid >> 5;

    wmma::fragment<wmma::accumulator, 16, 16, 16, float> acc[8];
    #pragma unroll
    for (int c = 0; c < 8; c++) wmma::fill_fragment(acc[c], 0.f);

    #pragma unroll
    for (int k = 0; k < 8; k++) {
        wmma::fragment<wmma::matrix_a, 16, 16, 16, __half, wmma::row_major> af;
        wmma::load_matrix_sync(af, As + warp * 16 * GW_LDA + k * 16, GW_LDA);
        #pragma unroll
        for (int c = 0; c < 8; c++) {
            wmma::fragment<wmma::matrix_b, 16, 16, 16, __half, wmma::row_major> bf;
            wmma::load_matrix_sync(bf, Ws + k * 16 * GW_LDA + c * 16, GW_LDA);
            wmma::mma_sync(acc[c], af, bf, acc[c]);
        }
    }
    __syncthreads();     // done reading As/Ws — reuse as fp32 staging

    float* Os = (float*)smraw;   // 128 x 128 fp32 (64 KB)
    #pragma unroll
    for (int c = 0; c < 8; c++)
        wmma::store_matrix_sync(Os + warp * 16 * 128 + c * 16, acc[c], 128, wmma::mem_row_major);
    __syncthreads();

    uint2* O2 = (uint2*)g_lin;
    #pragma unroll
    for (int i = 0; i < 16; i++) {
        int idx = tid + i * 256;            // 0..4095 over 128 rows x 32 float4
        int r = idx >> 5, c4 = idx & 31;
        int row = row0 + r;
        if (row < M) {
            float4 v = ((const float4*)Os)[idx];
            float dv = g_dinv[row];
            __half2 h0 = __floats2half2_rn(v.x * dv, v.y * dv);
            __half2 h1 = __floats2half2_rn(v.z * dv, v.w * dv);
            uint2 o;
            o.x = *(unsigned int*)&h0;
            o.y = *(unsigned int*)&h1;
            O2[(size_t)row * 32 + c4] = o;
        }
    }
}

// ---------------------------------------------------------------- aggregate: h[d] = b + dinv[d]*(lin'[d] + sum lin'[s])
// 16-lane group per node; fp16 packed accumulation (4 HADD2 per row-chunk).
__global__ void k_aggregate(const float* __restrict__ b, int n) {
    int grp  = (blockIdx.x * blockDim.x + threadIdx.x) >> 4;   // node id
    int lane = threadIdx.x & 15;                               // 16B chunk
    if (grp >= n) return;

    const uint4* lin4 = (const uint4*)g_lin;   // row stride = 16 uint4

    uint4 self = lin4[(size_t)grp * 16 + lane];
    __half2 a0 = *(__half2*)&self.x;
    __half2 a1 = *(__half2*)&self.y;
    __half2 a2 = *(__half2*)&self.z;
    __half2 a3 = *(__half2*)&self.w;

    int beg = g_rowptr[grp];
    int end = g_rowptr[grp + 1];
    int j = beg;
    for (; j + 8 <= end; j += 8) {
        int s0 = g_csrsrc[j];
        int s1 = g_csrsrc[j + 1];
        int s2 = g_csrsrc[j + 2];
        int s3 = g_csrsrc[j + 3];
        int s4 = g_csrsrc[j + 4];
        int s5 = g_csrsrc[j + 5];
        int s6 = g_csrsrc[j + 6];
        int s7 = g_csrsrc[j + 7];
        uint4 r0 = lin4[(size_t)s0 * 16 + lane];
        uint4 r1 = lin4[(size_t)s1 * 16 + lane];
        uint4 r2 = lin4[(size_t)s2 * 16 + lane];
        uint4 r3 = lin4[(size_t)s3 * 16 + lane];
        uint4 r4 = lin4[(size_t)s4 * 16 + lane];
        uint4 r5 = lin4[(size_t)s5 * 16 + lane];
        uint4 r6 = lin4[(size_t)s6 * 16 + lane];
        uint4 r7 = lin4[(size_t)s7 * 16 + lane];
        a0 = __hadd2(a0, *(__half2*)&r0.x); a1 = __hadd2(a1, *(__half2*)&r0.y);
        a2 = __hadd2(a2, *(__half2*)&r0.z); a3 = __hadd2(a3, *(__half2*)&r0.w);
        a0 = __hadd2(a0, *(__half2*)&r1.x); a1 = __hadd2(a1, *(__half2*)&r1.y);
        a2 = __hadd2(a2, *(__half2*)&r1.z); a3 = __hadd2(a3, *(__half2*)&r1.w);
        a0 = __hadd2(a0, *(__half2*)&r2.x); a1 = __hadd2(a1, *(__half2*)&r2.y);
        a2 = __hadd2(a2, *(__half2*)&r2.z); a3 = __hadd2(a3, *(__half2*)&r2.w);
        a0 = __hadd2(a0, *(__half2*)&r3.x); a1 = __hadd2(a1, *(__half2*)&r3.y);
        a2 = __hadd2(a2, *(__half2*)&r3.z); a3 = __hadd2(a3, *(__half2*)&r3.w);
        a0 = __hadd2(a0, *(__half2*)&r4.x); a1 = __hadd2(a1, *(__half2*)&r4.y);
        a2 = __hadd2(a2, *(__half2*)&r4.z); a3 = __hadd2(a3, *(__half2*)&r4.w);
        a0 = __hadd2(a0, *(__half2*)&r5.x); a1 = __hadd2(a1, *(__half2*)&r5.y);
        a2 = __hadd2(a2, *(__half2*)&r5.z); a3 = __hadd2(a3, *(__half2*)&r5.w);
        a0 = __hadd2(a0, *(__half2*)&r6.x); a1 = __hadd2(a1, *(__half2*)&r6.y);
        a2 = __hadd2(a2, *(__half2*)&r6.z); a3 = __hadd2(a3, *(__half2*)&r6.w);
        a0 = __hadd2(a0, *(__half2*)&r7.x); a1 = __hadd2(a1, *(__half2*)&r7.y);
        a2 = __hadd2(a2, *(__half2*)&r7.z); a3 = __hadd2(a3, *(__half2*)&r7.w);
    }
    for (; j < end; j++) {
        int s = g_csrsrc[j];
        uint4 r = lin4[(size_t)s * 16 + lane];
        a0 = __hadd2(a0, *(__half2*)&r.x); a1 = __hadd2(a1, *(__half2*)&r.y);
        a2 = __hadd2(a2, *(__half2*)&r.z); a3 = __hadd2(a3, *(__half2*)&r.w);
    }

    float2 f0 = __half22float2(a0);
    float2 f1 = __half22float2(a1);
    float2 f2 = __half22float2(a2);
    float2 f3 = __half22float2(a3);

    float di = g_dinv[grp];
    const float4* b4 = (const float4*)b;
    float4 bb0 = b4[lane * 2];
    float4 bb1 = b4[lane * 2 + 1];
    float4 o0, o1;
    o0.x = fmaf(f0.x, di, bb0.x);
    o0.y = fmaf(f0.y, di, bb0.y);
    o0.z = fmaf(f1.x, di, bb0.z);
    o0.w = fmaf(f1.y, di, bb0.w);
    o1.x = fmaf(f2.x, di, bb1.x);
    o1.y = fmaf(f2.y, di, bb1.y);
    o1.z = fmaf(f3.x, di, bb1.z);
    o1.w = fmaf(f3.y, di, bb1.w);
    float4* agg4 = (float4*)g_agg;
    agg4[(size_t)grp * 32 + lane * 2]     = o0;
    agg4[(size_t)grp * 32 + lane * 2 + 1] = o1;

    // fp16 relu copy for next layer's GEMM input
    __half2 h0 = __floats2half2_rn(fmaxf(o0.x, 0.f), fmaxf(o0.y, 0.f));
    __half2 h1 = __floats2half2_rn(fmaxf(o0.z, 0.f), fmaxf(o0.w, 0.f));
    __half2 h2 = __floats2half2_rn(fmaxf(o1.x, 0.f), fmaxf(o1.y, 0.f));
    __half2 h3 = __floats2half2_rn(fmaxf(o1.z, 0.f), fmaxf(o1.w, 0.f));
    uint4 oh;
    oh.x = *(unsigned int*)&h0;
    oh.y = *(unsigned int*)&h1;
    oh.z = *(unsigned int*)&h2;
    oh.w = *(unsigned int*)&h3;
    ((uint4*)g_aggh)[(size_t)grp * 16 + lane] = oh;
}

// ---------------------------------------------------------------- node projection as blocked GEMM:
// P[n, 32] = relu(g_agg[n,128]) @ Wp[128,32], Wp packed from Wfc rows 0..255.
#define PROJ_BM 64
__global__ void k_proj(const float* __restrict__ Wfc, int n) {
    __shared__ float Ws[128 * 32];        // Ws[k*32 + l]
    __shared__ float As[PROJ_BM * 128];   // 32 KB

    int tid = threadIdx.x;
    for (int idx = tid; idx < 128 * 32; idx += 256) {
        int k = idx >> 5, l = idx & 31;
        Ws[idx] = (l < 16) ? Wfc[k * 16 + l] : Wfc[(128 + k) * 16 + (l - 16)];
    }

    int row0 = blockIdx.x * PROJ_BM;
    float4* As4 = (float4*)As;
    const float4* A4 = (const float4*)g_agg;
    #pragma unroll
    for (int i = 0; i < 8; i++) {
        int idx = tid + i * 256;          // 0..2047
        int r   = idx >> 5;
        float4 v = make_float4(0.f, 0.f, 0.f, 0.f);
        if (row0 + r < n) {
            v = A4[(size_t)(row0 + r) * 32 + (idx & 31)];
            v.x = fmaxf(v.x, 0.f); v.y = fmaxf(v.y, 0.f);
            v.z = fmaxf(v.z, 0.f); v.w = fmaxf(v.w, 0.f);
        }
        As4[idx] = v;
    }
    __syncthreads();

    int warp = tid >> 5, lane = tid & 31;
    int rbase = warp * 8;

    float acc[8];
    #pragma unroll
    for (int r = 0; r < 8; r++) acc[r] = 0.f;

    #pragma unroll 4
    for (int k4 = 0; k4 < 32; k4++) {
        float w0 = Ws[(k4 * 4 + 0) * 32 + lane];
        float w1 = Ws[(k4 * 4 + 1) * 32 + lane];
        float w2 = Ws[(k4 * 4 + 2) * 32 + lane];
        float w3 = Ws[(k4 * 4 + 3) * 32 + lane];
        #pragma unroll
        for (int r = 0; r < 8; r++) {
            float4 a = As4[(rbase + r) * 32 + k4];
            acc[r] = fmaf(a.x, w0, acc[r]);
            acc[r] = fmaf(a.y, w1, acc[r]);
            acc[r] = fmaf(a.z, w2, acc[r]);
            acc[r] = fmaf(a.w, w3, acc[r]);
        }
    }

    #pragma unroll
    for (int r = 0; r < 8; r++) {
        int row = row0 + rbase + r;
        if (row < n) g_P[(size_t)row * 32 + lane] = acc[r];
    }
}

// ---------------------------------------------------------------- Q = eattr @ We  (wmma, fp16 in/out, fp32 acc)
// Block: 256 threads, 128 edges. We = Wfc rows 256..287 (32x16).
#define QG_LDA 40
__global__ void k_qgemm(const float* __restrict__ eattr, const float* __restrict__ Wfc, int e) {
    __shared__ __half eaS[128 * QG_LDA];   // 10240 B
    __shared__ __half WeS[32 * 16];        // 1024 B
    __shared__ float  QS [128 * 16];       // 8192 B

    int tid = threadIdx.x;
    int e0 = blockIdx.x * 128;

    if (tid < 256) {                        // 512 halves, 2 per thread
        WeS[tid]       = __float2half(Wfc[256 * 16 + tid]);
        WeS[tid + 256] = __float2half(Wfc[256 * 16 + tid + 256]);
    }
    const float4* ea4 = (const float4*)eattr;
    #pragma unroll
    for (int i = 0; i < 4; i++) {
        int idx = tid + i * 256;            // 0..1023
        int r = idx >> 3, c = idx & 7;      // row, float4-chunk
        float4 v = make_float4(0.f, 0.f, 0.f, 0.f);
        if (e0 + r < e) v = ea4[(size_t)(e0 + r) * 8 + c];
        __half2 h0 = __floats2half2_rn(v.x, v.y);
        __half2 h1 = __floats2half2_rn(v.z, v.w);
        uint2 o;
        o.x = *(unsigned int*)&h0;
        o.y = *(unsigned int*)&h1;
        *(uint2*)(eaS + r * QG_LDA + c * 4) = o;
    }
    __syncthreads();

    int warp = tid >> 5;
    wmma::fragment<wmma::accumulator, 16, 16, 16, float> acc;
    wmma::fill_fragment(acc, 0.f);
    #pragma unroll
    for (int k = 0; k < 2; k++) {
        wmma::fragment<wmma::matrix_a, 16, 16, 16, __half, wmma::row_major> af;
        wmma::fragment<wmma::matrix_b, 16, 16, 16, __half, wmma::row_major> bf;
        wmma::load_matrix_sync(af, eaS + warp * 16 * QG_LDA + k * 16, QG_LDA);
        wmma::load_matrix_sync(bf, WeS + k * 16 * 16, 16);
        wmma::mma_sync(acc, af, bf, acc);
    }
    wmma::store_matrix_sync(QS + warp * 16 * 16, acc, 16, wmma::mem_row_major);
    __syncthreads();

    // write Q fp16: each thread packs 8 floats -> 8 halves (16B)
    int r = tid >> 1, half = tid & 1;
    if (e0 + r < e) {
        const float* srcq = QS + r * 16 + half * 8;
        __half2 h0 = __floats2half2_rn(srcq[0], srcq[1]);
        __half2 h1 = __floats2half2_rn(srcq[2], srcq[3]);
        __half2 h2 = __floats2half2_rn(srcq[4], srcq[5]);
        __half2 h3 = __floats2half2_rn(srcq[6], srcq[7]);
        uint4 o;
        o.x = *(unsigned int*)&h0;
        o.y = *(unsigned int*)&h1;
        o.z = *(unsigned int*)&h2;
        o.w = *(unsigned int*)&h3;
        *(uint4*)(g_Q + (size_t)(e0 + r) * 16 + half * 8) = o;
    }
}

// ---------------------------------------------------------------- edge output: out = logsoftmax(P_src[s] + P_dst[d] + Q[e] + b)
#define EB 16   // edges per block (256 threads = 16 edges x 16 classes)
__global__ void k_edge3(const int* __restrict__ src, const int* __restrict__ dst,
                        const float* __restrict__ bfc, float* __restrict__ out, int e) {
    __shared__ float bs[CDIM];
    int tid = threadIdx.x;
    if (tid < CDIM) bs[tid] = bfc[tid];
    __syncthreads();

    int el = tid >> 4, c = tid & 15;
    int edge = blockIdx.x * EB + el;
    bool valid = edge < e;
    int ce = valid ? edge : e - 1;

    int s = src[ce], d = dst[ce];
    float q = __half2float(g_Q[(size_t)ce * 16 + c]);
    float acc = bs[c] + q + g_P[(size_t)s * 32 + c] + g_P[(size_t)d * 32 + 16 + c];

    float m = acc;
    #pragma unroll
    for (int off = 8; off; off >>= 1)
        m = fmaxf(m, __shfl_xor_sync(0xffffffffu, m, off));
    float ex = __expf(acc - m);
    float ss = ex;
    #pragma unroll
    for (int off = 8; off; off >>= 1)
        ss += __shfl_xor_sync(0xffffffffu, ss, off);
    float res = acc - m - __logf(ss);
    if (valid) out[(size_t)edge * CDIM + c] = res;
}

// ---------------------------------------------------------------- launch
extern "C" void kernel_launch(void* const* d_in, const int* in_sizes, int n_in,
                              void* d_out, int out_size) {
    const float* x     = (const float*)d_in[0];
    const int*   ei    = (const int*)  d_in[1];
    const float* eattr = (const float*)d_in[2];
    const float* W1 = (const float*)d_in[3];  const float* b1 = (const float*)d_in[4];
    const float* W2 = (const float*)d_in[5];  const float* b2 = (const float*)d_in[6];
    const float* W3 = (const float*)d_in[7];  const float* b3 = (const float*)d_in[8];
    const float* Wfc = (const float*)d_in[9]; const float* bfc = (const float*)d_in[10];
    float* out = (float*)d_out;

    int n = in_sizes[0] / HDIM;
    int e = in_sizes[1] / 2;
    const int* src = ei;
    const int* dst = ei + e;

    cudaFuncSetAttribute(k_gemm_wmma, cudaFuncAttributeMaxDynamicSharedMemorySize, GW_SMEM);

    int bn   = (n + 255) / 256;
    int be   = (e + 255) / 256;
    int bgem = (n + 127) / 128;
    int bagg = (n * 16 + 255) / 256;   // 16 lanes per node
    int bedg = (e + EB - 1) / EB;
    int bqg  = (e + 127) / 128;
    int nscan = (n + SCAN_B - 1) / SCAN_B;

    // ---- fp16 conversions (weights + x)
    __half* wh_base;
    cudaGetSymbolAddress((void**)&wh_base, g_Wh);
    __half* aggh_base;
    cudaGetSymbolAddress((void**)&aggh_base, g_aggh);
    k_cvt_half<<<(128 * 32 + 255) / 256, 256>>>(W1, wh_base,               128 * 32);
    k_cvt_half<<<(128 * 32 + 255) / 256, 256>>>(W2, wh_base + 128 * 128,   128 * 32);
    k_cvt_half<<<(128 * 32 + 255) / 256, 256>>>(W3, wh_base + 2 * 128 * 128, 128 * 32);
    k_cvt_half<<<(n * 32 + 255) / 256, 256>>>(x, aggh_base, n * 32);

    // ---- Q = eattr @ We (independent of everything else)
    k_qgemm<<<bqg, 256>>>(eattr, Wfc, e);

    // ---- CSR build (once; reused by all 3 layers) + degree norm
    k_cnt_zero<<<bn, 256>>>(n);
    k_hist    <<<be, 256>>>(dst, e);
    k_scan1   <<<nscan, SCAN_B>>>(n);
    k_scan2   <<<1, 128>>>(nscan);
    k_scan3   <<<nscan, SCAN_B>>>(n, e);
    k_fill    <<<be, 256>>>(src, dst, e);

    // ---- 3 GCN layers
    k_gemm_wmma<<<bgem, 256, GW_SMEM>>>(nullptr, n, 0);
    k_aggregate<<<bagg, 256>>>(b1, n);

    k_gemm_wmma<<<bgem, 256, GW_SMEM>>>(nullptr, n, 1);
    k_aggregate<<<bagg, 256>>>(b2, n);

    k_gemm_wmma<<<bgem, 256, GW_SMEM>>>(nullptr, n, 2);
    k_aggregate<<<bagg, 256>>>(b3, n);

    // ---- factored edge classifier
    k_proj <<<(n + PROJ_BM - 1) / PROJ_BM, 256>>>(Wfc, n);
    k_edge3<<<bedg, 256>>>(src, dst, bfc, out, e);
}

// round 12
// speedup vs baseline: 1.9841x; 1.1212x over previous
#include <cuda_runtime.h>
#include <cuda_fp16.h>
#include <mma.h>
#include <math.h>

using namespace nvcuda;

#define HDIM   128
#define NMAX   100000
#define EMAX   1000000
#define CDIM   16
#define SCAN_B 1024

// Scratch (static device globals — allocation-free per harness rules)
__device__ float  g_dinv[NMAX];
__device__ __half g_lin [(size_t)NMAX * HDIM];  // lin' = dinv[row]*(act(A)@W), fp16
__device__ __half g_aggh[(size_t)NMAX * HDIM];  // fp16: x, then relu(h) per layer
__device__ __half g_Wh  [3][128 * 128];         // fp16 weights
__device__ float  g_P   [(size_t)NMAX * 32];    // per-node [P_src(16) | P_dst(16)]
__device__ __half g_Q   [(size_t)EMAX * CDIM];  // per-edge eattr @ We (fp16)
__device__ int    g_cnt[NMAX];
__device__ int    g_rowptr[NMAX + 1];
__device__ int    g_cursor[NMAX];
__device__ int    g_csrsrc[EMAX];
__device__ int    g_blocksum[128];
__device__ int    g_blockoff[128];

// ---------------------------------------------------------------- fused prologue:
// blocks [0,bx): x -> fp16 g_aggh; [bx,bx+48): W1..W3 -> fp16; rest: cnt_zero.
__global__ void k_prologue(const float* __restrict__ x,
                           const float* __restrict__ W1,
                           const float* __restrict__ W2,
                           const float* __restrict__ W3,
                           int n, int bx) {
    int b = blockIdx.x, tid = threadIdx.x;
    if (b < bx) {
        int i = b * 256 + tid;
        if (i < n * 32) {
            float4 v = ((const float4*)x)[i];
            __half2 h0 = __floats2half2_rn(v.x, v.y);
            __half2 h1 = __floats2half2_rn(v.z, v.w);
            uint2 o;
            o.x = *(unsigned int*)&h0;
            o.y = *(unsigned int*)&h1;
            ((uint2*)g_aggh)[i] = o;
        }
    } else if (b < bx + 48) {
        int off = b - bx;                 // 0..47, 16 blocks per weight
        int w   = off >> 4;
        int i   = (off & 15) * 256 + tid; // 0..4095 float4
        const float* W = (w == 0) ? W1 : (w == 1) ? W2 : W3;
        float4 v = ((const float4*)W)[i];
        __half2 h0 = __floats2half2_rn(v.x, v.y);
        __half2 h1 = __floats2half2_rn(v.z, v.w);
        uint2 o;
        o.x = *(unsigned int*)&h0;
        o.y = *(unsigned int*)&h1;
        ((uint2*)g_Wh[w])[i] = o;
    } else {
        int i = (b - bx - 48) * 256 + tid;
        if (i < n) g_cnt[i] = 0;
    }
}

// ---------------------------------------------------------------- CSR scans
__global__ void k_scan1(int n) {
    __shared__ int sm[SCAN_B];
    int i = blockIdx.x * SCAN_B + threadIdx.x;
    int v = (i < n) ? g_cnt[i] : 0;
    if (i < n) g_dinv[i] = rsqrtf((float)v + 1.0f);   // +1 self-loop
    sm[threadIdx.x] = v;
    __syncthreads();
    #pragma unroll
    for (int off = 1; off < SCAN_B; off <<= 1) {
        int t = (threadIdx.x >= off) ? sm[threadIdx.x - off] : 0;
        __syncthreads();
        sm[threadIdx.x] += t;
        __syncthreads();
    }
    if (i < n) g_rowptr[i] = sm[threadIdx.x] - v;     // exclusive
    if (threadIdx.x == SCAN_B - 1) g_blocksum[blockIdx.x] = sm[SCAN_B - 1];
}
__global__ void k_scan2(int nb) {
    __shared__ int sm[128];
    int t = threadIdx.x;
    int v = (t < nb) ? g_blocksum[t] : 0;
    sm[t] = v;
    __syncthreads();
    #pragma unroll
    for (int off = 1; off < 128; off <<= 1) {
        int x = (t >= off) ? sm[t - off] : 0;
        __syncthreads();
        sm[t] += x;
        __syncthreads();
    }
    if (t < nb) g_blockoff[t] = sm[t] - v;            // exclusive
}
__global__ void k_scan3(int n, int e) {
    int i = blockIdx.x * SCAN_B + threadIdx.x;
    if (i < n) {
        int r = g_rowptr[i] + g_blockoff[blockIdx.x];
        g_rowptr[i] = r;
        g_cursor[i] = r;
    }
    if (i == 0) g_rowptr[n] = e;
}
__global__ void k_fill(const int* __restrict__ src, const int* __restrict__ dst, int e) {
    int i = blockIdx.x * blockDim.x + threadIdx.x;
    if (i < e) {
        int pos = atomicAdd(&g_cursor[dst[i]], 1);
        g_csrsrc[pos] = src[i];
    }
}

// ---------------------------------------------------------------- GEMM (tensor cores): lin' = fp16( dinv * (g_aggh @ Wh) )
#define GW_LDA  136
#define GW_SMEM (2 * 128 * GW_LDA * 2)   // 69632 B (also covers 64KB fp32 staging)
__global__ void k_gemm_wmma(const __half* __restrict__ Wh, int M, int widx) {
    extern __shared__ char smraw[];
    __half* As = (__half*)smraw;                         // 128 x 136
    __half* Ws = (__half*)(smraw + 128 * GW_LDA * 2);    // 128 x 136

    int tid = threadIdx.x;
    int row0 = blockIdx.x * 128;

    const uint4* W4 = (const uint4*)(g_Wh[widx]);
    #pragma unroll
    for (int i = 0; i < 8; i++) {
        int idx = tid + i * 256;
        int r = idx >> 4, c = (idx & 15) * 8;
        *(uint4*)(Ws + r * GW_LDA + c) = W4[idx];
    }
    const uint4* A4 = (const uint4*)g_aggh;
    #pragma unroll
    for (int i = 0; i < 8; i++) {
        int idx = tid + i * 256;
        int r = idx >> 4, c = (idx & 15) * 8;
        uint4 v = make_uint4(0u, 0u, 0u, 0u);
        if (row0 + r < M) v = A4[(size_t)(row0 + r) * 16 + (idx & 15)];
        *(uint4*)(As + r * GW_LDA + c) = v;
    }
    __syncthreads();

    int warp = tid >> 5;

    wmma::fragment<wmma::accumulator, 16, 16, 16, float> acc[8];
    #pragma unroll
    for (int c = 0; c < 8; c++) wmma::fill_fragment(acc[c], 0.f);

    #pragma unroll
    for (int k = 0; k < 8; k++) {
        wmma::fragment<wmma::matrix_a, 16, 16, 16, __half, wmma::row_major> af;
        wmma::load_matrix_sync(af, As + warp * 16 * GW_LDA + k * 16, GW_LDA);
        #pragma unroll
        for (int c = 0; c < 8; c++) {
            wmma::fragment<wmma::matrix_b, 16, 16, 16, __half, wmma::row_major> bf;
            wmma::load_matrix_sync(bf, Ws + k * 16 * GW_LDA + c * 16, GW_LDA);
            wmma::mma_sync(acc[c], af, bf, acc[c]);
        }
    }
    __syncthreads();     // done reading As/Ws — reuse as fp32 staging

    float* Os = (float*)smraw;   // 128 x 128 fp32 (64 KB)
    #pragma unroll
    for (int c = 0; c < 8; c++)
        wmma::store_matrix_sync(Os + warp * 16 * 128 + c * 16, acc[c], 128, wmma::mem_row_major);
    __syncthreads();

    uint2* O2 = (uint2*)g_lin;
    #pragma unroll
    for (int i = 0; i < 16; i++) {
        int idx = tid + i * 256;            // 0..4095 over 128 rows x 32 float4
        int r = idx >> 5, c4 = idx & 31;
        int row = row0 + r;
        if (row < M) {
            float4 v = ((const float4*)Os)[idx];
            float dv = g_dinv[row];
            __half2 h0 = __floats2half2_rn(v.x * dv, v.y * dv);
            __half2 h1 = __floats2half2_rn(v.z * dv, v.w * dv);
            uint2 o;
            o.x = *(unsigned int*)&h0;
            o.y = *(unsigned int*)&h1;
            O2[(size_t)row * 32 + c4] = o;
        }
    }
}

// ---------------------------------------------------------------- aggregate: h[d] = b + dinv[d]*(lin'[d] + sum lin'[s])
// 16-lane group per node; fp16 packed accumulation; writes ONLY fp16 relu(h).
__global__ void k_aggregate(const float* __restrict__ b, int n) {
    int grp  = (blockIdx.x * blockDim.x + threadIdx.x) >> 4;   // node id
    int lane = threadIdx.x & 15;                               // 16B chunk
    if (grp >= n) return;

    const uint4* lin4 = (const uint4*)g_lin;   // row stride = 16 uint4

    uint4 self = lin4[(size_t)grp * 16 + lane];
    __half2 a0 = *(__half2*)&self.x;
    __half2 a1 = *(__half2*)&self.y;
    __half2 a2 = *(__half2*)&self.z;
    __half2 a3 = *(__half2*)&self.w;

    int beg = g_rowptr[grp];
    int end = g_rowptr[grp + 1];
    int j = beg;
    for (; j + 8 <= end; j += 8) {
        int s0 = g_csrsrc[j];
        int s1 = g_csrsrc[j + 1];
        int s2 = g_csrsrc[j + 2];
        int s3 = g_csrsrc[j + 3];
        int s4 = g_csrsrc[j + 4];
        int s5 = g_csrsrc[j + 5];
        int s6 = g_csrsrc[j + 6];
        int s7 = g_csrsrc[j + 7];
        uint4 r0 = lin4[(size_t)s0 * 16 + lane];
        uint4 r1 = lin4[(size_t)s1 * 16 + lane];
        uint4 r2 = lin4[(size_t)s2 * 16 + lane];
        uint4 r3 = lin4[(size_t)s3 * 16 + lane];
        uint4 r4 = lin4[(size_t)s4 * 16 + lane];
        uint4 r5 = lin4[(size_t)s5 * 16 + lane];
        uint4 r6 = lin4[(size_t)s6 * 16 + lane];
        uint4 r7 = lin4[(size_t)s7 * 16 + lane];
        a0 = __hadd2(a0, *(__half2*)&r0.x); a1 = __hadd2(a1, *(__half2*)&r0.y);
        a2 = __hadd2(a2, *(__half2*)&r0.z); a3 = __hadd2(a3, *(__half2*)&r0.w);
        a0 = __hadd2(a0, *(__half2*)&r1.x); a1 = __hadd2(a1, *(__half2*)&r1.y);
        a2 = __hadd2(a2, *(__half2*)&r1.z); a3 = __hadd2(a3, *(__half2*)&r1.w);
        a0 = __hadd2(a0, *(__half2*)&r2.x); a1 = __hadd2(a1, *(__half2*)&r2.y);
        a2 = __hadd2(a2, *(__half2*)&r2.z); a3 = __hadd2(a3, *(__half2*)&r2.w);
        a0 = __hadd2(a0, *(__half2*)&r3.x); a1 = __hadd2(a1, *(__half2*)&r3.y);
        a2 = __hadd2(a2, *(__half2*)&r3.z); a3 = __hadd2(a3, *(__half2*)&r3.w);
        a0 = __hadd2(a0, *(__half2*)&r4.x); a1 = __hadd2(a1, *(__half2*)&r4.y);
        a2 = __hadd2(a2, *(__half2*)&r4.z); a3 = __hadd2(a3, *(__half2*)&r4.w);
        a0 = __hadd2(a0, *(__half2*)&r5.x); a1 = __hadd2(a1, *(__half2*)&r5.y);
        a2 = __hadd2(a2, *(__half2*)&r5.z); a3 = __hadd2(a3, *(__half2*)&r5.w);
        a0 = __hadd2(a0, *(__half2*)&r6.x); a1 = __hadd2(a1, *(__half2*)&r6.y);
        a2 = __hadd2(a2, *(__half2*)&r6.z); a3 = __hadd2(a3, *(__half2*)&r6.w);
        a0 = __hadd2(a0, *(__half2*)&r7.x); a1 = __hadd2(a1, *(__half2*)&r7.y);
        a2 = __hadd2(a2, *(__half2*)&r7.z); a3 = __hadd2(a3, *(__half2*)&r7.w);
    }
    for (; j < end; j++) {
        int s = g_csrsrc[j];
        uint4 r = lin4[(size_t)s * 16 + lane];
        a0 = __hadd2(a0, *(__half2*)&r.x); a1 = __hadd2(a1, *(__half2*)&r.y);
        a2 = __hadd2(a2, *(__half2*)&r.z); a3 = __hadd2(a3, *(__half2*)&r.w);
    }

    float2 f0 = __half22float2(a0);
    float2 f1 = __half22float2(a1);
    float2 f2 = __half22float2(a2);
    float2 f3 = __half22float2(a3);

    float di = g_dinv[grp];
    const float4* b4 = (const float4*)b;
    float4 bb0 = b4[lane * 2];
    float4 bb1 = b4[lane * 2 + 1];

    // relu(h) packed straight to fp16 (no fp32 store)
    __half2 h0 = __floats2half2_rn(fmaxf(fmaf(f0.x, di, bb0.x), 0.f),
                                   fmaxf(fmaf(f0.y, di, bb0.y), 0.f));
    __half2 h1 = __floats2half2_rn(fmaxf(fmaf(f1.x, di, bb0.z), 0.f),
                                   fmaxf(fmaf(f1.y, di, bb0.w), 0.f));
    __half2 h2 = __floats2half2_rn(fmaxf(fmaf(f2.x, di, bb1.x), 0.f),
                                   fmaxf(fmaf(f2.y, di, bb1.y), 0.f));
    __half2 h3 = __floats2half2_rn(fmaxf(fmaf(f3.x, di, bb1.z), 0.f),
                                   fmaxf(fmaf(f3.y, di, bb1.w), 0.f));
    uint4 oh;
    oh.x = *(unsigned int*)&h0;
    oh.y = *(unsigned int*)&h1;
    oh.z = *(unsigned int*)&h2;
    oh.w = *(unsigned int*)&h3;
    ((uint4*)g_aggh)[(size_t)grp * 16 + lane] = oh;
}

// ---------------------------------------------------------------- node projection:
// P[n, 32] = g_aggh[n,128] @ Wp[128,32]  (g_aggh already = relu(h3), fp16)
#define PROJ_BM 64
__global__ void k_proj(const float* __restrict__ Wfc, int n) {
    __shared__ float Ws[128 * 32];        // Ws[k*32 + l]
    __shared__ float As[PROJ_BM * 128];   // 32 KB

    int tid = threadIdx.x;
    for (int idx = tid; idx < 128 * 32; idx += 256) {
        int k = idx >> 5, l = idx & 31;
        Ws[idx] = (l < 16) ? Wfc[k * 16 + l] : Wfc[(128 + k) * 16 + (l - 16)];
    }

    int row0 = blockIdx.x * PROJ_BM;
    const uint4* A4 = (const uint4*)g_aggh;   // 16 uint4 per row
    #pragma unroll
    for (int i = 0; i < 4; i++) {
        int idx = tid + i * 256;              // 0..1023 over 64 rows x 16 chunks
        int r = idx >> 4, c = idx & 15;
        uint4 v = make_uint4(0u, 0u, 0u, 0u);
        if (row0 + r < n) v = A4[(size_t)(row0 + r) * 16 + c];
        __half2 h0 = *(__half2*)&v.x;
        __half2 h1 = *(__half2*)&v.y;
        __half2 h2 = *(__half2*)&v.z;
        __half2 h3 = *(__half2*)&v.w;
        float2 f0 = __half22float2(h0);
        float2 f1 = __half22float2(h1);
        float2 f2 = __half22float2(h2);
        float2 f3 = __half22float2(h3);
        float* dstp = As + r * 128 + c * 8;
        dstp[0] = f0.x; dstp[1] = f0.y; dstp[2] = f1.x; dstp[3] = f1.y;
        dstp[4] = f2.x; dstp[5] = f2.y; dstp[6] = f3.x; dstp[7] = f3.y;
    }
    __syncthreads();

    int warp = tid >> 5, lane = tid & 31;
    int rbase = warp * 8;
    float4* As4 = (float4*)As;

    float acc[8];
    #pragma unroll
    for (int r = 0; r < 8; r++) acc[r] = 0.f;

    #pragma unroll 4
    for (int k4 = 0; k4 < 32; k4++) {
        float w0 = Ws[(k4 * 4 + 0) * 32 + lane];
        float w1 = Ws[(k4 * 4 + 1) * 32 + lane];
        float w2 = Ws[(k4 * 4 + 2) * 32 + lane];
        float w3 = Ws[(k4 * 4 + 3) * 32 + lane];
        #pragma unroll
        for (int r = 0; r < 8; r++) {
            float4 a = As4[(rbase + r) * 32 + k4];
            acc[r] = fmaf(a.x, w0, acc[r]);
            acc[r] = fmaf(a.y, w1, acc[r]);
            acc[r] = fmaf(a.z, w2, acc[r]);
            acc[r] = fmaf(a.w, w3, acc[r]);
        }
    }

    #pragma unroll
    for (int r = 0; r < 8; r++) {
        int row = row0 + rbase + r;
        if (row < n) g_P[(size_t)row * 32 + lane] = acc[r];
    }
}

// ---------------------------------------------------------------- Q = eattr @ We (wmma) + fused degree histogram
#define QG_LDA 40
__global__ void k_qgemm(const float* __restrict__ eattr, const float* __restrict__ Wfc,
                        const int* __restrict__ dst, int e) {
    __shared__ __half eaS[128 * QG_LDA];   // 10240 B
    __shared__ __half WeS[32 * 16];        // 1024 B
    __shared__ float  QS [128 * 16];       // 8192 B

    int tid = threadIdx.x;
    int e0 = blockIdx.x * 128;

    // fused histogram (cnt zeroed by prologue; this kernel runs after it)
    if (tid < 128 && e0 + tid < e)
        atomicAdd(&g_cnt[dst[e0 + tid]], 1);

    if (tid < 256) {                        // 512 halves, 2 per thread
        WeS[tid]       = __float2half(Wfc[256 * 16 + tid]);
        WeS[tid + 256] = __float2half(Wfc[256 * 16 + tid + 256]);
    }
    const float4* ea4 = (const float4*)eattr;
    #pragma unroll
    for (int i = 0; i < 4; i++) {
        int idx = tid + i * 256;            // 0..1023
        int r = idx >> 3, c = idx & 7;      // row, float4-chunk
        float4 v = make_float4(0.f, 0.f, 0.f, 0.f);
        if (e0 + r < e) v = ea4[(size_t)(e0 + r) * 8 + c];
        __half2 h0 = __floats2half2_rn(v.x, v.y);
        __half2 h1 = __floats2half2_rn(v.z, v.w);
        uint2 o;
        o.x = *(unsigned int*)&h0;
        o.y = *(unsigned int*)&h1;
        *(uint2*)(eaS + r * QG_LDA + c * 4) = o;
    }
    __syncthreads();

    int warp = tid >> 5;
    wmma::fragment<wmma::accumulator, 16, 16, 16, float> acc;
    wmma::fill_fragment(acc, 0.f);
    #pragma unroll
    for (int k = 0; k < 2; k++) {
        wmma::fragment<wmma::matrix_a, 16, 16, 16, __half, wmma::row_major> af;
        wmma::fragment<wmma::matrix_b, 16, 16, 16, __half, wmma::row_major> bf;
        wmma::load_matrix_sync(af, eaS + warp * 16 * QG_LDA + k * 16, QG_LDA);
        wmma::load_matrix_sync(bf, WeS + k * 16 * 16, 16);
        wmma::mma_sync(acc, af, bf, acc);
    }
    wmma::store_matrix_sync(QS + warp * 16 * 16, acc, 16, wmma::mem_row_major);
    __syncthreads();

    int r = tid >> 1, half = tid & 1;
    if (e0 + r < e) {
        const float* srcq = QS + r * 16 + half * 8;
        __half2 h0 = __floats2half2_rn(srcq[0], srcq[1]);
        __half2 h1 = __floats2half2_rn(srcq[2], srcq[3]);
        __half2 h2 = __floats2half2_rn(srcq[4], srcq[5]);
        __half2 h3 = __floats2half2_rn(srcq[6], srcq[7]);
        uint4 o;
        o.x = *(unsigned int*)&h0;
        o.y = *(unsigned int*)&h1;
        o.z = *(unsigned int*)&h2;
        o.w = *(unsigned int*)&h3;
        *(uint4*)(g_Q + (size_t)(e0 + r) * 16 + half * 8) = o;
    }
}

// ---------------------------------------------------------------- edge output: out = logsoftmax(P_src[s] + P_dst[d] + Q[e] + b)
#define EB 16   // edges per block (256 threads = 16 edges x 16 classes)
__global__ void k_edge3(const int* __restrict__ src, const int* __restrict__ dst,
                        const float* __restrict__ bfc, float* __restrict__ out, int e) {
    __shared__ float bs[CDIM];
    int tid = threadIdx.x;
    if (tid < CDIM) bs[tid] = bfc[tid];
    __syncthreads();

    int el = tid >> 4, c = tid & 15;
    int edge = blockIdx.x * EB + el;
    bool valid = edge < e;
    int ce = valid ? edge : e - 1;

    int s = src[ce], d = dst[ce];
    float q = __half2float(g_Q[(size_t)ce * 16 + c]);
    float acc = bs[c] + q + g_P[(size_t)s * 32 + c] + g_P[(size_t)d * 32 + 16 + c];

    float m = acc;
    #pragma unroll
    for (int off = 8; off; off >>= 1)
        m = fmaxf(m, __shfl_xor_sync(0xffffffffu, m, off));
    float ex = __expf(acc - m);
    float ss = ex;
    #pragma unroll
    for (int off = 8; off; off >>= 1)
        ss += __shfl_xor_sync(0xffffffffu, ss, off);
    float res = acc - m - __logf(ss);
    if (valid) out[(size_t)edge * CDIM + c] = res;
}

// ---------------------------------------------------------------- launch
extern "C" void kernel_launch(void* const* d_in, const int* in_sizes, int n_in,
                              void* d_out, int out_size) {
    const float* x     = (const float*)d_in[0];
    const int*   ei    = (const int*)  d_in[1];
    const float* eattr = (const float*)d_in[2];
    const float* W1 = (const float*)d_in[3];  const float* b1 = (const float*)d_in[4];
    const float* W2 = (const float*)d_in[5];  const float* b2 = (const float*)d_in[6];
    const float* W3 = (const float*)d_in[7];  const float* b3 = (const float*)d_in[8];
    const float* Wfc = (const float*)d_in[9]; const float* bfc = (const float*)d_in[10];
    float* out = (float*)d_out;

    int n = in_sizes[0] / HDIM;
    int e = in_sizes[1] / 2;
    const int* src = ei;
    const int* dst = ei + e;

    cudaFuncSetAttribute(k_gemm_wmma, cudaFuncAttributeMaxDynamicSharedMemorySize, GW_SMEM);

    int bx   = (n * 32 + 255) / 256;          // x-convert blocks
    int bc   = (n + 255) / 256;               // cnt_zero blocks
    int be   = (e + 255) / 256;
    int bgem = (n + 127) / 128;
    int bagg = (n * 16 + 255) / 256;          // 16 lanes per node
    int bedg = (e + EB - 1) / EB;
    int bqg  = (e + 127) / 128;
    int nscan = (n + SCAN_B - 1) / SCAN_B;

    // ---- fused prologue: x/W fp16 converts + cnt_zero
    k_prologue<<<bx + 48 + bc, 256>>>(x, W1, W2, W3, n, bx);

    // ---- Q GEMM + fused degree histogram
    k_qgemm<<<bqg, 256>>>(eattr, Wfc, dst, e);

    // ---- CSR scans + fill
    k_scan1<<<nscan, SCAN_B>>>(n);
    k_scan2<<<1, 128>>>(nscan);
    k_scan3<<<nscan, SCAN_B>>>(n, e);
    k_fill <<<be, 256>>>(src, dst, e);

    // ---- 3 GCN layers
    k_gemm_wmma<<<bgem, 256, GW_SMEM>>>(nullptr, n, 0);
    k_aggregate<<<bagg, 256>>>(b1, n);

    k_gemm_wmma<<<bgem, 256, GW_SMEM>>>(nullptr, n, 1);
    k_aggregate<<<bagg, 256>>>(b2, n);

    k_gemm_wmma<<<bgem, 256, GW_SMEM>>>(nullptr, n, 2);
    k_aggregate<<<bagg, 256>>>(b3, n);

    // ---- factored edge classifier
    k_proj <<<(n + PROJ_BM - 1) / PROJ_BM, 256>>>(Wfc, n);
    k_edge3<<<bedg, 256>>>(src, dst, bfc, out, e);
}